// round 11
// baseline (speedup 1.0000x reference)
#include <cuda_runtime.h>
#include <cuda_bf16.h>
#include <cuda_fp16.h>
#include <cstdint>

#define NN 50000
#define EE 800000
#define NCLS 40
#define NBLK 49   // ceil(NN/1024)

// ---------------- device scratch (static, allocation-free) ----------------
__device__ __align__(16) __half g_H1h[NN * 128];          // layer1 features (fp16)
__device__ __align__(16) float g_out1[NN * 128];          // layer1 output after ELU (fp32: feeds bf16 split)
__device__ __align__(16) __half g_H2h[NN * NCLS + 64];    // layer2 features (fp16, padded)
__device__ __align__(16) float g_asrc1[NN * 8];
__device__ __align__(16) float g_adst1[NN * 8];
__device__ float g_asrc2[NN];
__device__ float g_adst2[NN];
__device__ int g_deg[NN];        // self-restoring: count adds, fill subtracts
__device__ int g_rowptr[NN + 1];
__device__ int g_csr[EE];
__device__ int g_bsum[64];

__device__ __forceinline__ float lrelu(float x) { return x > 0.f ? x : 0.2f * x; }

// ---------------- CSR build ----------------
__global__ void count_kernel(const int* __restrict__ ei) {
    int q = blockIdx.x * blockDim.x + threadIdx.x;
    if (q < EE / 4) {
        int4 d4 = __ldg((const int4*)(ei + EE) + q);
        atomicAdd(&g_deg[d4.x], 1);
        atomicAdd(&g_deg[d4.y], 1);
        atomicAdd(&g_deg[d4.z], 1);
        atomicAdd(&g_deg[d4.w], 1);
    }
}

__global__ void blockscan_kernel() {
    __shared__ int wsum[32];
    int b = blockIdx.x, t = threadIdx.x;
    int i = b * 1024 + t;
    int lane = t & 31, wid = t >> 5;
    int x = (i < NN) ? g_deg[i] : 0;
#pragma unroll
    for (int off = 1; off < 32; off <<= 1) {
        int y = __shfl_up_sync(0xffffffffu, x, off);
        if (lane >= off) x += y;
    }
    if (lane == 31) wsum[wid] = x;
    __syncthreads();
    if (wid == 0) {
        int s = wsum[lane];
#pragma unroll
        for (int off = 1; off < 32; off <<= 1) {
            int y = __shfl_up_sync(0xffffffffu, s, off);
            if (lane >= off) s += y;
        }
        wsum[lane] = s;
    }
    __syncthreads();
    int incl = x + (wid > 0 ? wsum[wid - 1] : 0);
    if (i < NN) g_rowptr[i + 1] = incl;
    if (t == 1023) g_bsum[b] = incl;
}

__global__ void addoff_kernel() {
    __shared__ int s_off;
    int b = blockIdx.x, t = threadIdx.x;
    if (t < 32) {
        int v = (t < b) ? g_bsum[t] : 0;
        if (t + 32 < b) v += g_bsum[t + 32];
#pragma unroll
        for (int off = 16; off > 0; off >>= 1)
            v += __shfl_xor_sync(0xffffffffu, v, off);
        if (t == 0) s_off = v;
    }
    __syncthreads();
    int i = b * 1024 + t;
    if (i < NN) g_rowptr[i + 1] += s_off;
    if (i == 0) g_rowptr[0] = 0;
}

__global__ void fill_kernel(const int* __restrict__ ei) {
    int q = blockIdx.x * blockDim.x + threadIdx.x;
    if (q < EE / 4) {
        int4 s4 = __ldg((const int4*)ei + q);
        int4 d4 = __ldg((const int4*)(ei + EE) + q);
        int p;
        p = atomicSub(&g_deg[d4.x], 1); g_csr[g_rowptr[d4.x] + p - 1] = s4.x;
        p = atomicSub(&g_deg[d4.y], 1); g_csr[g_rowptr[d4.y] + p - 1] = s4.y;
        p = atomicSub(&g_deg[d4.z], 1); g_csr[g_rowptr[d4.z] + p - 1] = s4.z;
        p = atomicSub(&g_deg[d4.w], 1); g_csr[g_rowptr[d4.w] + p - 1] = s4.w;
    }
}

// ---------------- shared MMA helpers ----------------
__device__ __forceinline__ void mma_bf16(float* c, const uint32_t* a, uint32_t b0, uint32_t b1) {
    asm volatile(
        "mma.sync.aligned.m16n8k16.row.col.f32.bf16.bf16.f32 "
        "{%0,%1,%2,%3}, {%4,%5,%6,%7}, {%8,%9}, {%0,%1,%2,%3};"
        : "+f"(c[0]), "+f"(c[1]), "+f"(c[2]), "+f"(c[3])
        : "r"(a[0]), "r"(a[1]), "r"(a[2]), "r"(a[3]), "r"(b0), "r"(b1));
}

__device__ __forceinline__ uint32_t pack_bf2(float a, float b) {
    __nv_bfloat162 h = __floats2bfloat162_rn(a, b);
    return *(uint32_t*)&h;
}

// ---------------- GEMM1 via mma.sync bf16 (3-term hi/lo split) + fused attn1 ----
#define A_STRIDE 36
#define B_STRIDE 136
#define SM_AHI 0
#define SM_ALO (128 * A_STRIDE)
#define SM_BHI (2 * 128 * A_STRIDE)
#define SM_BLO (2 * 128 * A_STRIDE + 32 * B_STRIDE)
#define SM_WORDS (2 * 128 * A_STRIDE + 2 * 32 * B_STRIDE)

__global__ void __launch_bounds__(256, 1)
gemm1_mma_kernel(const float* __restrict__ x, const float* __restrict__ W1,
                 const float* __restrict__ as, const float* __restrict__ ad) {
    extern __shared__ uint32_t sm[];
    uint32_t* Ahi = sm + SM_AHI;
    uint32_t* Alo = sm + SM_ALO;
    uint32_t* Bhi = sm + SM_BHI;
    uint32_t* Blo = sm + SM_BLO;

    int t = threadIdx.x, wid = t >> 5, lane = t & 31;
    int wr = wid & 3, wc = wid >> 2;
    int nbase = blockIdx.x * 128;

    float c[2][8][4];
#pragma unroll
    for (int rs = 0; rs < 2; rs++)
#pragma unroll
        for (int nf = 0; nf < 8; nf++)
#pragma unroll
            for (int q = 0; q < 4; q++) c[rs][nf][q] = 0.f;

    for (int kc = 0; kc < 2; kc++) {
        if (kc) __syncthreads();
#pragma unroll
        for (int i = 0; i < 8; i++) {
            int idx = t + 256 * i;
            int r = idx >> 4, c4 = idx & 15;
            int node = nbase + r;
            float4 v = make_float4(0.f, 0.f, 0.f, 0.f);
            if (node < NN) v = ((const float4*)x)[node * 32 + kc * 16 + c4];
            uint32_t h0 = pack_bf2(v.x, v.y), h1 = pack_bf2(v.z, v.w);
            __nv_bfloat162 hh0 = *(__nv_bfloat162*)&h0;
            __nv_bfloat162 hh1 = *(__nv_bfloat162*)&h1;
            uint32_t l0 = pack_bf2(v.x - __bfloat162float(hh0.x), v.y - __bfloat162float(hh0.y));
            uint32_t l1 = pack_bf2(v.z - __bfloat162float(hh1.x), v.w - __bfloat162float(hh1.y));
            int w = r * A_STRIDE + c4 * 2;
            Ahi[w] = h0; Ahi[w + 1] = h1;
            Alo[w] = l0; Alo[w + 1] = l1;
        }
#pragma unroll
        for (int i = 0; i < 32; i++) {
            int idx = t + 256 * i;
            int k = idx >> 7, j = idx & 127;
            float w = W1[(kc * 64 + k) * 128 + j];
            __nv_bfloat16 hi = __float2bfloat16(w);
            __nv_bfloat16 lo = __float2bfloat16(w - __bfloat162float(hi));
            int word = (k >> 1) * B_STRIDE + j;
            ((__nv_bfloat16*)(Bhi + word))[k & 1] = hi;
            ((__nv_bfloat16*)(Blo + word))[k & 1] = lo;
        }
        __syncthreads();

#pragma unroll
        for (int kk = 0; kk < 4; kk++) {
            uint32_t ah[2][4], al[2][4];
#pragma unroll
            for (int rs = 0; rs < 2; rs++) {
                int row = wr * 32 + rs * 16 + (lane >> 2);
                int base = row * A_STRIDE + kk * 8 + (lane & 3);
                ah[rs][0] = Ahi[base];
                ah[rs][1] = Ahi[base + 8 * A_STRIDE];
                ah[rs][2] = Ahi[base + 4];
                ah[rs][3] = Ahi[base + 8 * A_STRIDE + 4];
                al[rs][0] = Alo[base];
                al[rs][1] = Alo[base + 8 * A_STRIDE];
                al[rs][2] = Alo[base + 4];
                al[rs][3] = Alo[base + 8 * A_STRIDE + 4];
            }
#pragma unroll
            for (int nf = 0; nf < 8; nf++) {
                int j = wc * 64 + nf * 8 + (lane >> 2);
                int bw = (kk * 8 + (lane & 3)) * B_STRIDE + j;
                uint32_t bh0 = Bhi[bw], bh1 = Bhi[bw + 4 * B_STRIDE];
                uint32_t bl0 = Blo[bw], bl1 = Blo[bw + 4 * B_STRIDE];
#pragma unroll
                for (int rs = 0; rs < 2; rs++) {
                    mma_bf16(c[rs][nf], ah[rs], bh0, bh1);
                    mma_bf16(c[rs][nf], ah[rs], bl0, bl1);
                    mma_bf16(c[rs][nf], al[rs], bh0, bh1);
                }
            }
        }
    }

#pragma unroll
    for (int rs = 0; rs < 2; rs++) {
#pragma unroll
        for (int hh = 0; hh < 2; hh++) {
            int row = wr * 32 + rs * 16 + (lane >> 2) + hh * 8;
            int node = nbase + row;
            float ss[4] = {0.f, 0.f, 0.f, 0.f};
            float dd[4] = {0.f, 0.f, 0.f, 0.f};
#pragma unroll
            for (int nf = 0; nf < 8; nf++) {
                float v0 = c[rs][nf][hh * 2];
                float v1 = c[rs][nf][hh * 2 + 1];
                int col = wc * 64 + nf * 8 + (lane & 3) * 2;
                if (node < NN)
                    *(__half2*)&g_H1h[node * 128 + col] = __floats2half2_rn(v0, v1);
                int hp = nf >> 1;
                int wcol = (nf & 1) * 8 + (lane & 3) * 2;
                int hb = (wc * 4 + hp) * 16 + wcol;
                ss[hp] += v0 * __ldg(&as[hb]) + v1 * __ldg(&as[hb + 1]);
                dd[hp] += v0 * __ldg(&ad[hb]) + v1 * __ldg(&ad[hb + 1]);
            }
#pragma unroll
            for (int hp = 0; hp < 4; hp++) {
                ss[hp] += __shfl_xor_sync(0xffffffffu, ss[hp], 1);
                ss[hp] += __shfl_xor_sync(0xffffffffu, ss[hp], 2);
                dd[hp] += __shfl_xor_sync(0xffffffffu, dd[hp], 1);
                dd[hp] += __shfl_xor_sync(0xffffffffu, dd[hp], 2);
            }
            if ((lane & 3) == 0 && node < NN) {
#pragma unroll
                for (int hp = 0; hp < 4; hp++) {
                    g_asrc1[node * 8 + wc * 4 + hp] = ss[hp];
                    g_adst1[node * 8 + wc * 4 + hp] = dd[hp];
                }
            }
        }
    }
}

// ---------------- layer-1 aggregation: warp per dst, fp16 gathers, unroll 4 ----
__device__ __forceinline__ float4 ld_h1_row4(int node, int l) {
    uint2 u = __ldg((const uint2*)(g_H1h + node * 128) + l);
    float2 a = __half22float2(*(__half2*)&u.x);
    float2 b = __half22float2(*(__half2*)&u.y);
    return make_float4(a.x, a.y, b.x, b.y);
}

__global__ void agg1_kernel(const float* __restrict__ b1) {
    int w = (blockIdx.x * blockDim.x + threadIdx.x) >> 5;
    int l = threadIdx.x & 31;
    if (w >= NN) return;
    int d = w;
    int start = g_rowptr[d], end = g_rowptr[d + 1];
    int hl = l >> 2;

    float adh = __ldg(&g_adst1[d * 8 + hl]);
    float wself = __expf(lrelu(__ldg(&g_asrc1[d * 8 + hl]) + adh));

    float den0 = wself, den1 = 0.f, den2 = 0.f, den3 = 0.f;
    float4 acc0, acc1, acc2, acc3;
    {
        float4 v = ld_h1_row4(d, l);
        acc0.x = wself * v.x; acc0.y = wself * v.y;
        acc0.z = wself * v.z; acc0.w = wself * v.w;
        acc1 = make_float4(0.f, 0.f, 0.f, 0.f);
        acc2 = make_float4(0.f, 0.f, 0.f, 0.f);
        acc3 = make_float4(0.f, 0.f, 0.f, 0.f);
    }

    int e = start;
    for (; e + 3 < end; e += 4) {
        int s0 = __ldg(&g_csr[e]);
        int s1 = __ldg(&g_csr[e + 1]);
        int s2 = __ldg(&g_csr[e + 2]);
        int s3 = __ldg(&g_csr[e + 3]);
        float w0 = __expf(lrelu(__ldg(&g_asrc1[s0 * 8 + hl]) + adh));
        float w1 = __expf(lrelu(__ldg(&g_asrc1[s1 * 8 + hl]) + adh));
        float w2 = __expf(lrelu(__ldg(&g_asrc1[s2 * 8 + hl]) + adh));
        float w3 = __expf(lrelu(__ldg(&g_asrc1[s3 * 8 + hl]) + adh));
        float4 v0 = ld_h1_row4(s0, l);
        float4 v1 = ld_h1_row4(s1, l);
        float4 v2 = ld_h1_row4(s2, l);
        float4 v3 = ld_h1_row4(s3, l);
        den0 += w0; den1 += w1; den2 += w2; den3 += w3;
        acc0.x += w0 * v0.x; acc0.y += w0 * v0.y; acc0.z += w0 * v0.z; acc0.w += w0 * v0.w;
        acc1.x += w1 * v1.x; acc1.y += w1 * v1.y; acc1.z += w1 * v1.z; acc1.w += w1 * v1.w;
        acc2.x += w2 * v2.x; acc2.y += w2 * v2.y; acc2.z += w2 * v2.z; acc2.w += w2 * v2.w;
        acc3.x += w3 * v3.x; acc3.y += w3 * v3.y; acc3.z += w3 * v3.z; acc3.w += w3 * v3.w;
    }
    for (; e < end; e++) {
        int s0 = __ldg(&g_csr[e]);
        float w0 = __expf(lrelu(__ldg(&g_asrc1[s0 * 8 + hl]) + adh));
        float4 v0 = ld_h1_row4(s0, l);
        den0 += w0;
        acc0.x += w0 * v0.x; acc0.y += w0 * v0.y;
        acc0.z += w0 * v0.z; acc0.w += w0 * v0.w;
    }

    float inv = 1.f / ((den0 + den1) + (den2 + den3));
    float4 bb = ((const float4*)b1)[l];
    float4 r;
    r.x = ((acc0.x + acc1.x) + (acc2.x + acc3.x)) * inv + bb.x;
    r.y = ((acc0.y + acc1.y) + (acc2.y + acc3.y)) * inv + bb.y;
    r.z = ((acc0.z + acc1.z) + (acc2.z + acc3.z)) * inv + bb.z;
    r.w = ((acc0.w + acc1.w) + (acc2.w + acc3.w)) * inv + bb.w;
    r.x = r.x > 0.f ? r.x : __expf(r.x) - 1.f;
    r.y = r.y > 0.f ? r.y : __expf(r.y) - 1.f;
    r.z = r.z > 0.f ? r.z : __expf(r.z) - 1.f;
    r.w = r.w > 0.f ? r.w : __expf(r.w) - 1.f;
    ((float4*)g_out1)[d * 32 + l] = r;
}

// ---------------- GEMM2 via mma.sync bf16 split + fused attn2 ----------------
#define A2_STRIDE 68
#define B2_STRIDE 44
#define SM2_ALO (128 * A2_STRIDE)
#define SM2_BHI (2 * 128 * A2_STRIDE)
#define SM2_BLO (2 * 128 * A2_STRIDE + 64 * B2_STRIDE)
#define SM2_WORDS (2 * 128 * A2_STRIDE + 2 * 64 * B2_STRIDE)

__global__ void __launch_bounds__(256, 1)
gemm2_mma_kernel(const float* __restrict__ W2,
                 const float* __restrict__ as2, const float* __restrict__ ad2) {
    extern __shared__ uint32_t sm[];
    uint32_t* Ahi = sm;
    uint32_t* Alo = sm + SM2_ALO;
    uint32_t* Bhi = sm + SM2_BHI;
    uint32_t* Blo = sm + SM2_BLO;

    int t = threadIdx.x, wid = t >> 5, lane = t & 31;
    int nbase = blockIdx.x * 128;

#pragma unroll
    for (int i = 0; i < 16; i++) {
        int idx = t + 256 * i;
        int r = idx >> 5, c4 = idx & 31;
        int node = nbase + r;
        float4 v = make_float4(0.f, 0.f, 0.f, 0.f);
        if (node < NN) v = ((const float4*)g_out1)[node * 32 + c4];
        uint32_t h0 = pack_bf2(v.x, v.y), h1 = pack_bf2(v.z, v.w);
        __nv_bfloat162 hh0 = *(__nv_bfloat162*)&h0;
        __nv_bfloat162 hh1 = *(__nv_bfloat162*)&h1;
        uint32_t l0 = pack_bf2(v.x - __bfloat162float(hh0.x), v.y - __bfloat162float(hh0.y));
        uint32_t l1 = pack_bf2(v.z - __bfloat162float(hh1.x), v.w - __bfloat162float(hh1.y));
        int w = r * A2_STRIDE + c4 * 2;
        Ahi[w] = h0; Ahi[w + 1] = h1;
        Alo[w] = l0; Alo[w + 1] = l1;
    }
    for (int idx = t; idx < 128 * NCLS; idx += 256) {
        int k = idx / NCLS, j = idx % NCLS;
        float w = W2[idx];
        __nv_bfloat16 hi = __float2bfloat16(w);
        __nv_bfloat16 lo = __float2bfloat16(w - __bfloat162float(hi));
        int word = (k >> 1) * B2_STRIDE + j;
        ((__nv_bfloat16*)(Bhi + word))[k & 1] = hi;
        ((__nv_bfloat16*)(Blo + word))[k & 1] = lo;
    }
    __syncthreads();

    float c[5][4];
#pragma unroll
    for (int nf = 0; nf < 5; nf++)
#pragma unroll
        for (int q = 0; q < 4; q++) c[nf][q] = 0.f;

#pragma unroll
    for (int kk = 0; kk < 8; kk++) {
        int base = (wid * 16 + (lane >> 2)) * A2_STRIDE + kk * 8 + (lane & 3);
        uint32_t ah[4], al[4];
        ah[0] = Ahi[base];
        ah[1] = Ahi[base + 8 * A2_STRIDE];
        ah[2] = Ahi[base + 4];
        ah[3] = Ahi[base + 8 * A2_STRIDE + 4];
        al[0] = Alo[base];
        al[1] = Alo[base + 8 * A2_STRIDE];
        al[2] = Alo[base + 4];
        al[3] = Alo[base + 8 * A2_STRIDE + 4];
#pragma unroll
        for (int nf = 0; nf < 5; nf++) {
            int j = nf * 8 + (lane >> 2);
            int bw = (kk * 8 + (lane & 3)) * B2_STRIDE + j;
            uint32_t bh0 = Bhi[bw], bh1 = Bhi[bw + 4 * B2_STRIDE];
            uint32_t bl0 = Blo[bw], bl1 = Blo[bw + 4 * B2_STRIDE];
            mma_bf16(c[nf], ah, bh0, bh1);
            mma_bf16(c[nf], ah, bl0, bl1);
            mma_bf16(c[nf], al, bh0, bh1);
        }
    }

#pragma unroll
    for (int hh = 0; hh < 2; hh++) {
        int row = wid * 16 + (lane >> 2) + hh * 8;
        int node = nbase + row;
        float ps = 0.f, pd = 0.f;
#pragma unroll
        for (int nf = 0; nf < 5; nf++) {
            float v0 = c[nf][hh * 2];
            float v1 = c[nf][hh * 2 + 1];
            int col = nf * 8 + (lane & 3) * 2;
            if (node < NN)
                *(__half2*)&g_H2h[node * NCLS + col] = __floats2half2_rn(v0, v1);
            ps += v0 * __ldg(&as2[col]) + v1 * __ldg(&as2[col + 1]);
            pd += v0 * __ldg(&ad2[col]) + v1 * __ldg(&ad2[col + 1]);
        }
        ps += __shfl_xor_sync(0xffffffffu, ps, 1);
        ps += __shfl_xor_sync(0xffffffffu, ps, 2);
        pd += __shfl_xor_sync(0xffffffffu, pd, 1);
        pd += __shfl_xor_sync(0xffffffffu, pd, 2);
        if ((lane & 3) == 0 && node < NN) {
            g_asrc2[node] = ps;
            g_adst2[node] = pd;
        }
    }
}

// ---------------- layer-2 aggregation: warp per dst, fp16 gathers ----------------
// Lanes 0..19 each own a column pair {2l, 2l+1} (one half2 per edge).
__global__ void agg2_kernel(const float* __restrict__ b2, float* __restrict__ out) {
    int w = (blockIdx.x * blockDim.x + threadIdx.x) >> 5;
    int l = threadIdx.x & 31;
    if (w >= NN) return;
    int d = w;
    int start = g_rowptr[d], end = g_rowptr[d + 1];
    bool act = (l < 20);

    float adst = __ldg(&g_adst2[d]);
    float wself = __expf(lrelu(__ldg(&g_asrc2[d]) + adst));

    float den0 = wself, den1 = 0.f, den2 = 0.f, den3 = 0.f;
    float2 acc0 = make_float2(0.f, 0.f), acc1 = acc0, acc2 = acc0, acc3 = acc0;
    if (act) {
        float2 v = __half22float2(__ldg((const __half2*)(g_H2h + d * NCLS) + l));
        acc0.x = wself * v.x; acc0.y = wself * v.y;
    }

    int e = start;
    for (; e + 3 < end; e += 4) {
        int s0 = __ldg(&g_csr[e]);
        int s1 = __ldg(&g_csr[e + 1]);
        int s2 = __ldg(&g_csr[e + 2]);
        int s3 = __ldg(&g_csr[e + 3]);
        float w0 = __expf(lrelu(__ldg(&g_asrc2[s0]) + adst));
        float w1 = __expf(lrelu(__ldg(&g_asrc2[s1]) + adst));
        float w2 = __expf(lrelu(__ldg(&g_asrc2[s2]) + adst));
        float w3 = __expf(lrelu(__ldg(&g_asrc2[s3]) + adst));
        den0 += w0; den1 += w1; den2 += w2; den3 += w3;
        if (act) {
            float2 v0 = __half22float2(__ldg((const __half2*)(g_H2h + s0 * NCLS) + l));
            float2 v1 = __half22float2(__ldg((const __half2*)(g_H2h + s1 * NCLS) + l));
            float2 v2 = __half22float2(__ldg((const __half2*)(g_H2h + s2 * NCLS) + l));
            float2 v3 = __half22float2(__ldg((const __half2*)(g_H2h + s3 * NCLS) + l));
            acc0.x += w0 * v0.x; acc0.y += w0 * v0.y;
            acc1.x += w1 * v1.x; acc1.y += w1 * v1.y;
            acc2.x += w2 * v2.x; acc2.y += w2 * v2.y;
            acc3.x += w3 * v3.x; acc3.y += w3 * v3.y;
        }
    }
    for (; e < end; e++) {
        int s0 = __ldg(&g_csr[e]);
        float w0 = __expf(lrelu(__ldg(&g_asrc2[s0]) + adst));
        den0 += w0;
        if (act) {
            float2 v0 = __half22float2(__ldg((const __half2*)(g_H2h + s0 * NCLS) + l));
            acc0.x += w0 * v0.x; acc0.y += w0 * v0.y;
        }
    }

    if (act) {
        float inv = 1.f / ((den0 + den1) + (den2 + den3));
        float ox = ((acc0.x + acc1.x) + (acc2.x + acc3.x)) * inv + __ldg(&b2[2 * l]);
        float oy = ((acc0.y + acc1.y) + (acc2.y + acc3.y)) * inv + __ldg(&b2[2 * l + 1]);
        *(float2*)&out[d * NCLS + 2 * l] = make_float2(ox, oy);
    }
}

// ---------------- launch ----------------
static cudaStream_t g_s2 = nullptr;
static cudaEvent_t g_evFork = nullptr, g_evJoin = nullptr;

extern "C" void kernel_launch(void* const* d_in, const int* in_sizes, int n_in,
                              void* d_out, int out_size) {
    const float* x   = (const float*)d_in[0];
    const int*   ei  = (const int*)d_in[1];     // int32 (JAX x64 disabled)
    const float* W1  = (const float*)d_in[2];
    const float* as1 = (const float*)d_in[3];
    const float* ad1 = (const float*)d_in[4];
    const float* b1  = (const float*)d_in[5];
    const float* W2  = (const float*)d_in[6];
    const float* as2 = (const float*)d_in[7];
    const float* ad2 = (const float*)d_in[8];
    const float* b2  = (const float*)d_in[9];
    float* out = (float*)d_out;

    if (g_s2 == nullptr) {
        cudaStreamCreateWithFlags(&g_s2, cudaStreamNonBlocking);
        cudaEventCreateWithFlags(&g_evFork, cudaEventDisableTiming);
        cudaEventCreateWithFlags(&g_evJoin, cudaEventDisableTiming);
        cudaFuncSetAttribute(gemm1_mma_kernel,
                             cudaFuncAttributeMaxDynamicSharedMemorySize, SM_WORDS * 4);
        cudaFuncSetAttribute(gemm2_mma_kernel,
                             cudaFuncAttributeMaxDynamicSharedMemorySize, SM2_WORDS * 4);
    }

    // fork: CSR build on side stream (g_deg is self-restoring; no zero pass)
    cudaEventRecord(g_evFork, 0);
    cudaStreamWaitEvent(g_s2, g_evFork, 0);

    count_kernel<<<(EE / 4 + 255) / 256, 256, 0, g_s2>>>(ei);
    blockscan_kernel<<<NBLK, 1024, 0, g_s2>>>();
    addoff_kernel<<<NBLK, 1024, 0, g_s2>>>();
    fill_kernel<<<(EE / 4 + 255) / 256, 256, 0, g_s2>>>(ei);
    cudaEventRecord(g_evJoin, g_s2);

    // main stream: tensor-core GEMM1 with fused attn1
    gemm1_mma_kernel<<<(NN + 127) / 128, 256, SM_WORDS * 4>>>(x, W1, as1, ad1);

    // join: aggregation needs both
    cudaStreamWaitEvent(0, g_evJoin, 0);
    agg1_kernel<<<(NN * 32 + 255) / 256, 256>>>(b1);

    gemm2_mma_kernel<<<(NN + 127) / 128, 256, SM2_WORDS * 4>>>(W2, as2, ad2);
    agg2_kernel<<<(NN * 32 + 255) / 256, 256>>>(b2, out);
}

// round 12
// speedup vs baseline: 1.0310x; 1.0310x over previous
#include <cuda_runtime.h>
#include <cuda_bf16.h>
#include <cstdint>

#define NN 50000
#define EE 800000
#define NCLS 40
#define NBLK 49     // ceil(NN/1024)
#define HALF0 25088 // 196 tiles of 128
#define HALF1 (NN - HALF0)

// ---------------- device scratch (static, allocation-free) ----------------
__device__ __align__(16) float g_H1[NN * 128];    // layer1 features (fp32)
__device__ __align__(16) float g_out1[NN * 128];  // layer1 output after ELU
__device__ __align__(16) float g_H2[NN * NCLS];   // layer2 features
__device__ __align__(16) float g_asrc1[NN * 8];
__device__ __align__(16) float g_adst1[NN * 8];
__device__ float g_asrc2[NN];
__device__ float g_adst2[NN];
__device__ int g_deg[NN];        // self-restoring: count adds, fill subtracts
__device__ int g_rowptr[NN + 1];
__device__ int g_csr[EE];
__device__ int g_bsum[64];

__device__ __forceinline__ float lrelu(float x) { return x > 0.f ? x : 0.2f * x; }

// ---------------- CSR build ----------------
__global__ void count_kernel(const int* __restrict__ ei) {
    int q = blockIdx.x * blockDim.x + threadIdx.x;
    if (q < EE / 4) {
        int4 d4 = __ldg((const int4*)(ei + EE) + q);
        atomicAdd(&g_deg[d4.x], 1);
        atomicAdd(&g_deg[d4.y], 1);
        atomicAdd(&g_deg[d4.z], 1);
        atomicAdd(&g_deg[d4.w], 1);
    }
}

__global__ void blockscan_kernel() {
    __shared__ int wsum[32];
    int b = blockIdx.x, t = threadIdx.x;
    int i = b * 1024 + t;
    int lane = t & 31, wid = t >> 5;
    int x = (i < NN) ? g_deg[i] : 0;
#pragma unroll
    for (int off = 1; off < 32; off <<= 1) {
        int y = __shfl_up_sync(0xffffffffu, x, off);
        if (lane >= off) x += y;
    }
    if (lane == 31) wsum[wid] = x;
    __syncthreads();
    if (wid == 0) {
        int s = wsum[lane];
#pragma unroll
        for (int off = 1; off < 32; off <<= 1) {
            int y = __shfl_up_sync(0xffffffffu, s, off);
            if (lane >= off) s += y;
        }
        wsum[lane] = s;
    }
    __syncthreads();
    int incl = x + (wid > 0 ? wsum[wid - 1] : 0);
    if (i < NN) g_rowptr[i + 1] = incl;
    if (t == 1023) g_bsum[b] = incl;
}

__global__ void addoff_kernel() {
    __shared__ int s_off;
    int b = blockIdx.x, t = threadIdx.x;
    if (t < 32) {
        int v = (t < b) ? g_bsum[t] : 0;
        if (t + 32 < b) v += g_bsum[t + 32];
#pragma unroll
        for (int off = 16; off > 0; off >>= 1)
            v += __shfl_xor_sync(0xffffffffu, v, off);
        if (t == 0) s_off = v;
    }
    __syncthreads();
    int i = b * 1024 + t;
    if (i < NN) g_rowptr[i + 1] += s_off;
    if (i == 0) g_rowptr[0] = 0;
}

__global__ void fill_kernel(const int* __restrict__ ei) {
    int q = blockIdx.x * blockDim.x + threadIdx.x;
    if (q < EE / 4) {
        int4 s4 = __ldg((const int4*)ei + q);
        int4 d4 = __ldg((const int4*)(ei + EE) + q);
        int r0 = __ldg(&g_rowptr[d4.x]);
        int r1 = __ldg(&g_rowptr[d4.y]);
        int r2 = __ldg(&g_rowptr[d4.z]);
        int r3 = __ldg(&g_rowptr[d4.w]);
        int p0 = atomicSub(&g_deg[d4.x], 1);
        int p1 = atomicSub(&g_deg[d4.y], 1);
        int p2 = atomicSub(&g_deg[d4.z], 1);
        int p3 = atomicSub(&g_deg[d4.w], 1);
        g_csr[r0 + p0 - 1] = s4.x;
        g_csr[r1 + p1 - 1] = s4.y;
        g_csr[r2 + p2 - 1] = s4.z;
        g_csr[r3 + p3 - 1] = s4.w;
    }
}

// ---------------- shared MMA helpers ----------------
__device__ __forceinline__ void mma_bf16(float* c, const uint32_t* a, uint32_t b0, uint32_t b1) {
    asm volatile(
        "mma.sync.aligned.m16n8k16.row.col.f32.bf16.bf16.f32 "
        "{%0,%1,%2,%3}, {%4,%5,%6,%7}, {%8,%9}, {%0,%1,%2,%3};"
        : "+f"(c[0]), "+f"(c[1]), "+f"(c[2]), "+f"(c[3])
        : "r"(a[0]), "r"(a[1]), "r"(a[2]), "r"(a[3]), "r"(b0), "r"(b1));
}

__device__ __forceinline__ uint32_t pack_bf2(float a, float b) {
    __nv_bfloat162 h = __floats2bfloat162_rn(a, b);
    return *(uint32_t*)&h;
}

// ---------------- GEMM1 via mma.sync bf16 (3-term hi/lo split) + fused attn1 ----
#define A_STRIDE 36
#define B_STRIDE 136
#define SM_AHI 0
#define SM_ALO (128 * A_STRIDE)
#define SM_BHI (2 * 128 * A_STRIDE)
#define SM_BLO (2 * 128 * A_STRIDE + 32 * B_STRIDE)
#define SM_WORDS (2 * 128 * A_STRIDE + 2 * 32 * B_STRIDE)

__global__ void __launch_bounds__(256, 1)
gemm1_mma_kernel(const float* __restrict__ x, const float* __restrict__ W1,
                 const float* __restrict__ as, const float* __restrict__ ad) {
    extern __shared__ uint32_t sm[];
    uint32_t* Ahi = sm + SM_AHI;
    uint32_t* Alo = sm + SM_ALO;
    uint32_t* Bhi = sm + SM_BHI;
    uint32_t* Blo = sm + SM_BLO;

    int t = threadIdx.x, wid = t >> 5, lane = t & 31;
    int wr = wid & 3, wc = wid >> 2;
    int nbase = blockIdx.x * 128;

    float c[2][8][4];
#pragma unroll
    for (int rs = 0; rs < 2; rs++)
#pragma unroll
        for (int nf = 0; nf < 8; nf++)
#pragma unroll
            for (int q = 0; q < 4; q++) c[rs][nf][q] = 0.f;

    for (int kc = 0; kc < 2; kc++) {
        if (kc) __syncthreads();
#pragma unroll
        for (int i = 0; i < 8; i++) {
            int idx = t + 256 * i;
            int r = idx >> 4, c4 = idx & 15;
            int node = nbase + r;
            float4 v = make_float4(0.f, 0.f, 0.f, 0.f);
            if (node < NN) v = ((const float4*)x)[node * 32 + kc * 16 + c4];
            uint32_t h0 = pack_bf2(v.x, v.y), h1 = pack_bf2(v.z, v.w);
            __nv_bfloat162 hh0 = *(__nv_bfloat162*)&h0;
            __nv_bfloat162 hh1 = *(__nv_bfloat162*)&h1;
            uint32_t l0 = pack_bf2(v.x - __bfloat162float(hh0.x), v.y - __bfloat162float(hh0.y));
            uint32_t l1 = pack_bf2(v.z - __bfloat162float(hh1.x), v.w - __bfloat162float(hh1.y));
            int w = r * A_STRIDE + c4 * 2;
            Ahi[w] = h0; Ahi[w + 1] = h1;
            Alo[w] = l0; Alo[w + 1] = l1;
        }
#pragma unroll
        for (int i = 0; i < 32; i++) {
            int idx = t + 256 * i;
            int k = idx >> 7, j = idx & 127;
            float w = W1[(kc * 64 + k) * 128 + j];
            __nv_bfloat16 hi = __float2bfloat16(w);
            __nv_bfloat16 lo = __float2bfloat16(w - __bfloat162float(hi));
            int word = (k >> 1) * B_STRIDE + j;
            ((__nv_bfloat16*)(Bhi + word))[k & 1] = hi;
            ((__nv_bfloat16*)(Blo + word))[k & 1] = lo;
        }
        __syncthreads();

#pragma unroll
        for (int kk = 0; kk < 4; kk++) {
            uint32_t ah[2][4], al[2][4];
#pragma unroll
            for (int rs = 0; rs < 2; rs++) {
                int row = wr * 32 + rs * 16 + (lane >> 2);
                int base = row * A_STRIDE + kk * 8 + (lane & 3);
                ah[rs][0] = Ahi[base];
                ah[rs][1] = Ahi[base + 8 * A_STRIDE];
                ah[rs][2] = Ahi[base + 4];
                ah[rs][3] = Ahi[base + 8 * A_STRIDE + 4];
                al[rs][0] = Alo[base];
                al[rs][1] = Alo[base + 8 * A_STRIDE];
                al[rs][2] = Alo[base + 4];
                al[rs][3] = Alo[base + 8 * A_STRIDE + 4];
            }
#pragma unroll
            for (int nf = 0; nf < 8; nf++) {
                int j = wc * 64 + nf * 8 + (lane >> 2);
                int bw = (kk * 8 + (lane & 3)) * B_STRIDE + j;
                uint32_t bh0 = Bhi[bw], bh1 = Bhi[bw + 4 * B_STRIDE];
                uint32_t bl0 = Blo[bw], bl1 = Blo[bw + 4 * B_STRIDE];
#pragma unroll
                for (int rs = 0; rs < 2; rs++) {
                    mma_bf16(c[rs][nf], ah[rs], bh0, bh1);
                    mma_bf16(c[rs][nf], ah[rs], bl0, bl1);
                    mma_bf16(c[rs][nf], al[rs], bh0, bh1);
                }
            }
        }
    }

#pragma unroll
    for (int rs = 0; rs < 2; rs++) {
#pragma unroll
        for (int hh = 0; hh < 2; hh++) {
            int row = wr * 32 + rs * 16 + (lane >> 2) + hh * 8;
            int node = nbase + row;
            float ss[4] = {0.f, 0.f, 0.f, 0.f};
            float dd[4] = {0.f, 0.f, 0.f, 0.f};
#pragma unroll
            for (int nf = 0; nf < 8; nf++) {
                float v0 = c[rs][nf][hh * 2];
                float v1 = c[rs][nf][hh * 2 + 1];
                int col = wc * 64 + nf * 8 + (lane & 3) * 2;
                if (node < NN)
                    *(float2*)&g_H1[node * 128 + col] = make_float2(v0, v1);
                int hp = nf >> 1;
                int wcol = (nf & 1) * 8 + (lane & 3) * 2;
                int hb = (wc * 4 + hp) * 16 + wcol;
                ss[hp] += v0 * __ldg(&as[hb]) + v1 * __ldg(&as[hb + 1]);
                dd[hp] += v0 * __ldg(&ad[hb]) + v1 * __ldg(&ad[hb + 1]);
            }
#pragma unroll
            for (int hp = 0; hp < 4; hp++) {
                ss[hp] += __shfl_xor_sync(0xffffffffu, ss[hp], 1);
                ss[hp] += __shfl_xor_sync(0xffffffffu, ss[hp], 2);
                dd[hp] += __shfl_xor_sync(0xffffffffu, dd[hp], 1);
                dd[hp] += __shfl_xor_sync(0xffffffffu, dd[hp], 2);
            }
            if ((lane & 3) == 0 && node < NN) {
#pragma unroll
                for (int hp = 0; hp < 4; hp++) {
                    g_asrc1[node * 8 + wc * 4 + hp] = ss[hp];
                    g_adst1[node * 8 + wc * 4 + hp] = dd[hp];
                }
            }
        }
    }
}

// ---------------- layer-1 aggregation: warp per dst, unroll 8 (MLP 8) ----------
__global__ void agg1_kernel(const float* __restrict__ b1, int base, int cnt) {
    int w = base + ((blockIdx.x * blockDim.x + threadIdx.x) >> 5);
    int l = threadIdx.x & 31;
    if (w >= base + cnt || w >= NN) return;
    int d = w;
    int start = g_rowptr[d], end = g_rowptr[d + 1];
    int hl = l >> 2;

    float adh = __ldg(&g_adst1[d * 8 + hl]);
    float wself = __expf(lrelu(__ldg(&g_asrc1[d * 8 + hl]) + adh));

    float den0 = wself, den1 = 0.f, den2 = 0.f, den3 = 0.f;
    float4 acc0, acc1, acc2, acc3;
    {
        float4 v = __ldg(((const float4*)g_H1) + d * 32 + l);
        acc0.x = wself * v.x; acc0.y = wself * v.y;
        acc0.z = wself * v.z; acc0.w = wself * v.w;
        acc1 = make_float4(0.f, 0.f, 0.f, 0.f);
        acc2 = make_float4(0.f, 0.f, 0.f, 0.f);
        acc3 = make_float4(0.f, 0.f, 0.f, 0.f);
    }

    int e = start;
    for (; e + 7 < end; e += 8) {
        int s0 = __ldg(&g_csr[e]);
        int s1 = __ldg(&g_csr[e + 1]);
        int s2 = __ldg(&g_csr[e + 2]);
        int s3 = __ldg(&g_csr[e + 3]);
        int s4 = __ldg(&g_csr[e + 4]);
        int s5 = __ldg(&g_csr[e + 5]);
        int s6 = __ldg(&g_csr[e + 6]);
        int s7 = __ldg(&g_csr[e + 7]);
        float w0 = __expf(lrelu(__ldg(&g_asrc1[s0 * 8 + hl]) + adh));
        float w1 = __expf(lrelu(__ldg(&g_asrc1[s1 * 8 + hl]) + adh));
        float w2 = __expf(lrelu(__ldg(&g_asrc1[s2 * 8 + hl]) + adh));
        float w3 = __expf(lrelu(__ldg(&g_asrc1[s3 * 8 + hl]) + adh));
        float w4 = __expf(lrelu(__ldg(&g_asrc1[s4 * 8 + hl]) + adh));
        float w5 = __expf(lrelu(__ldg(&g_asrc1[s5 * 8 + hl]) + adh));
        float w6 = __expf(lrelu(__ldg(&g_asrc1[s6 * 8 + hl]) + adh));
        float w7 = __expf(lrelu(__ldg(&g_asrc1[s7 * 8 + hl]) + adh));
        float4 v0 = __ldg(((const float4*)g_H1) + s0 * 32 + l);
        float4 v1 = __ldg(((const float4*)g_H1) + s1 * 32 + l);
        float4 v2 = __ldg(((const float4*)g_H1) + s2 * 32 + l);
        float4 v3 = __ldg(((const float4*)g_H1) + s3 * 32 + l);
        float4 v4 = __ldg(((const float4*)g_H1) + s4 * 32 + l);
        float4 v5 = __ldg(((const float4*)g_H1) + s5 * 32 + l);
        float4 v6 = __ldg(((const float4*)g_H1) + s6 * 32 + l);
        float4 v7 = __ldg(((const float4*)g_H1) + s7 * 32 + l);
        den0 += w0 + w4; den1 += w1 + w5; den2 += w2 + w6; den3 += w3 + w7;
        acc0.x += w0 * v0.x + w4 * v4.x; acc0.y += w0 * v0.y + w4 * v4.y;
        acc0.z += w0 * v0.z + w4 * v4.z; acc0.w += w0 * v0.w + w4 * v4.w;
        acc1.x += w1 * v1.x + w5 * v5.x; acc1.y += w1 * v1.y + w5 * v5.y;
        acc1.z += w1 * v1.z + w5 * v5.z; acc1.w += w1 * v1.w + w5 * v5.w;
        acc2.x += w2 * v2.x + w6 * v6.x; acc2.y += w2 * v2.y + w6 * v6.y;
        acc2.z += w2 * v2.z + w6 * v6.z; acc2.w += w2 * v2.w + w6 * v6.w;
        acc3.x += w3 * v3.x + w7 * v7.x; acc3.y += w3 * v3.y + w7 * v7.y;
        acc3.z += w3 * v3.z + w7 * v7.z; acc3.w += w3 * v3.w + w7 * v7.w;
    }
    for (; e + 1 < end; e += 2) {
        int s0 = __ldg(&g_csr[e]);
        int s1 = __ldg(&g_csr[e + 1]);
        float w0 = __expf(lrelu(__ldg(&g_asrc1[s0 * 8 + hl]) + adh));
        float w1 = __expf(lrelu(__ldg(&g_asrc1[s1 * 8 + hl]) + adh));
        float4 v0 = __ldg(((const float4*)g_H1) + s0 * 32 + l);
        float4 v1 = __ldg(((const float4*)g_H1) + s1 * 32 + l);
        den0 += w0; den1 += w1;
        acc0.x += w0 * v0.x; acc0.y += w0 * v0.y; acc0.z += w0 * v0.z; acc0.w += w0 * v0.w;
        acc1.x += w1 * v1.x; acc1.y += w1 * v1.y; acc1.z += w1 * v1.z; acc1.w += w1 * v1.w;
    }
    if (e < end) {
        int s0 = __ldg(&g_csr[e]);
        float w0 = __expf(lrelu(__ldg(&g_asrc1[s0 * 8 + hl]) + adh));
        float4 v0 = __ldg(((const float4*)g_H1) + s0 * 32 + l);
        den0 += w0;
        acc0.x += w0 * v0.x; acc0.y += w0 * v0.y;
        acc0.z += w0 * v0.z; acc0.w += w0 * v0.w;
    }

    float inv = 1.f / ((den0 + den1) + (den2 + den3));
    float4 bb = ((const float4*)b1)[l];
    float4 r;
    r.x = ((acc0.x + acc1.x) + (acc2.x + acc3.x)) * inv + bb.x;
    r.y = ((acc0.y + acc1.y) + (acc2.y + acc3.y)) * inv + bb.y;
    r.z = ((acc0.z + acc1.z) + (acc2.z + acc3.z)) * inv + bb.z;
    r.w = ((acc0.w + acc1.w) + (acc2.w + acc3.w)) * inv + bb.w;
    r.x = r.x > 0.f ? r.x : __expf(r.x) - 1.f;
    r.y = r.y > 0.f ? r.y : __expf(r.y) - 1.f;
    r.z = r.z > 0.f ? r.z : __expf(r.z) - 1.f;
    r.w = r.w > 0.f ? r.w : __expf(r.w) - 1.f;
    ((float4*)g_out1)[d * 32 + l] = r;
}

// ---------------- GEMM2 via mma.sync bf16 split + fused attn2 (tile offset) ----
#define A2_STRIDE 68
#define B2_STRIDE 44
#define SM2_ALO (128 * A2_STRIDE)
#define SM2_BHI (2 * 128 * A2_STRIDE)
#define SM2_BLO (2 * 128 * A2_STRIDE + 64 * B2_STRIDE)
#define SM2_WORDS (2 * 128 * A2_STRIDE + 2 * 64 * B2_STRIDE)

__global__ void __launch_bounds__(256, 1)
gemm2_mma_kernel(const float* __restrict__ W2,
                 const float* __restrict__ as2, const float* __restrict__ ad2,
                 int tile0) {
    extern __shared__ uint32_t sm[];
    uint32_t* Ahi = sm;
    uint32_t* Alo = sm + SM2_ALO;
    uint32_t* Bhi = sm + SM2_BHI;
    uint32_t* Blo = sm + SM2_BLO;

    int t = threadIdx.x, wid = t >> 5, lane = t & 31;
    int nbase = (tile0 + blockIdx.x) * 128;

#pragma unroll
    for (int i = 0; i < 16; i++) {
        int idx = t + 256 * i;
        int r = idx >> 5, c4 = idx & 31;
        int node = nbase + r;
        float4 v = make_float4(0.f, 0.f, 0.f, 0.f);
        if (node < NN) v = ((const float4*)g_out1)[node * 32 + c4];
        uint32_t h0 = pack_bf2(v.x, v.y), h1 = pack_bf2(v.z, v.w);
        __nv_bfloat162 hh0 = *(__nv_bfloat162*)&h0;
        __nv_bfloat162 hh1 = *(__nv_bfloat162*)&h1;
        uint32_t l0 = pack_bf2(v.x - __bfloat162float(hh0.x), v.y - __bfloat162float(hh0.y));
        uint32_t l1 = pack_bf2(v.z - __bfloat162float(hh1.x), v.w - __bfloat162float(hh1.y));
        int w = r * A2_STRIDE + c4 * 2;
        Ahi[w] = h0; Ahi[w + 1] = h1;
        Alo[w] = l0; Alo[w + 1] = l1;
    }
    for (int idx = t; idx < 128 * NCLS; idx += 256) {
        int k = idx / NCLS, j = idx % NCLS;
        float w = W2[idx];
        __nv_bfloat16 hi = __float2bfloat16(w);
        __nv_bfloat16 lo = __float2bfloat16(w - __bfloat162float(hi));
        int word = (k >> 1) * B2_STRIDE + j;
        ((__nv_bfloat16*)(Bhi + word))[k & 1] = hi;
        ((__nv_bfloat16*)(Blo + word))[k & 1] = lo;
    }
    __syncthreads();

    float c[5][4];
#pragma unroll
    for (int nf = 0; nf < 5; nf++)
#pragma unroll
        for (int q = 0; q < 4; q++) c[nf][q] = 0.f;

#pragma unroll
    for (int kk = 0; kk < 8; kk++) {
        int base = (wid * 16 + (lane >> 2)) * A2_STRIDE + kk * 8 + (lane & 3);
        uint32_t ah[4], al[4];
        ah[0] = Ahi[base];
        ah[1] = Ahi[base + 8 * A2_STRIDE];
        ah[2] = Ahi[base + 4];
        ah[3] = Ahi[base + 8 * A2_STRIDE + 4];
        al[0] = Alo[base];
        al[1] = Alo[base + 8 * A2_STRIDE];
        al[2] = Alo[base + 4];
        al[3] = Alo[base + 8 * A2_STRIDE + 4];
#pragma unroll
        for (int nf = 0; nf < 5; nf++) {
            int j = nf * 8 + (lane >> 2);
            int bw = (kk * 8 + (lane & 3)) * B2_STRIDE + j;
            uint32_t bh0 = Bhi[bw], bh1 = Bhi[bw + 4 * B2_STRIDE];
            uint32_t bl0 = Blo[bw], bl1 = Blo[bw + 4 * B2_STRIDE];
            mma_bf16(c[nf], ah, bh0, bh1);
            mma_bf16(c[nf], ah, bl0, bl1);
            mma_bf16(c[nf], al, bh0, bh1);
        }
    }

#pragma unroll
    for (int hh = 0; hh < 2; hh++) {
        int row = wid * 16 + (lane >> 2) + hh * 8;
        int node = nbase + row;
        float ps = 0.f, pd = 0.f;
#pragma unroll
        for (int nf = 0; nf < 5; nf++) {
            float v0 = c[nf][hh * 2];
            float v1 = c[nf][hh * 2 + 1];
            int col = nf * 8 + (lane & 3) * 2;
            if (node < NN)
                *(float2*)&g_H2[node * NCLS + col] = make_float2(v0, v1);
            ps += v0 * __ldg(&as2[col]) + v1 * __ldg(&as2[col + 1]);
            pd += v0 * __ldg(&ad2[col]) + v1 * __ldg(&ad2[col + 1]);
        }
        ps += __shfl_xor_sync(0xffffffffu, ps, 1);
        ps += __shfl_xor_sync(0xffffffffu, ps, 2);
        pd += __shfl_xor_sync(0xffffffffu, pd, 1);
        pd += __shfl_xor_sync(0xffffffffu, pd, 2);
        if ((lane & 3) == 0 && node < NN) {
            g_asrc2[node] = ps;
            g_adst2[node] = pd;
        }
    }
}

// ---------------- layer-2 aggregation: warp per dst, single pass, unroll 4 ----
__global__ void agg2_kernel(const float* __restrict__ b2, float* __restrict__ out) {
    int w = (blockIdx.x * blockDim.x + threadIdx.x) >> 5;
    int l = threadIdx.x & 31;
    if (w >= NN) return;
    int d = w;
    int start = g_rowptr[d], end = g_rowptr[d + 1];

    float adst = __ldg(&g_adst2[d]);
    float wself = __expf(lrelu(__ldg(&g_asrc2[d]) + adst));

    float den0 = wself, den1 = 0.f, den2 = 0.f, den3 = 0.f;
    float accA0 = wself * __ldg(&g_H2[d * NCLS + l]);
    float accA1 = 0.f, accA2 = 0.f, accA3 = 0.f;
    float accB0 = (l < 8) ? wself * __ldg(&g_H2[d * NCLS + 32 + l]) : 0.f;
    float accB1 = 0.f, accB2 = 0.f, accB3 = 0.f;

    int e = start;
    for (; e + 3 < end; e += 4) {
        int s0 = __ldg(&g_csr[e]);
        int s1 = __ldg(&g_csr[e + 1]);
        int s2 = __ldg(&g_csr[e + 2]);
        int s3 = __ldg(&g_csr[e + 3]);
        float w0 = __expf(lrelu(__ldg(&g_asrc2[s0]) + adst));
        float w1 = __expf(lrelu(__ldg(&g_asrc2[s1]) + adst));
        float w2 = __expf(lrelu(__ldg(&g_asrc2[s2]) + adst));
        float w3 = __expf(lrelu(__ldg(&g_asrc2[s3]) + adst));
        den0 += w0; den1 += w1; den2 += w2; den3 += w3;
        accA0 += w0 * __ldg(&g_H2[s0 * NCLS + l]);
        accA1 += w1 * __ldg(&g_H2[s1 * NCLS + l]);
        accA2 += w2 * __ldg(&g_H2[s2 * NCLS + l]);
        accA3 += w3 * __ldg(&g_H2[s3 * NCLS + l]);
        if (l < 8) {
            accB0 += w0 * __ldg(&g_H2[s0 * NCLS + 32 + l]);
            accB1 += w1 * __ldg(&g_H2[s1 * NCLS + 32 + l]);
            accB2 += w2 * __ldg(&g_H2[s2 * NCLS + 32 + l]);
            accB3 += w3 * __ldg(&g_H2[s3 * NCLS + 32 + l]);
        }
    }
    for (; e < end; e++) {
        int s0 = __ldg(&g_csr[e]);
        float w0 = __expf(lrelu(__ldg(&g_asrc2[s0]) + adst));
        den0 += w0;
        accA0 += w0 * __ldg(&g_H2[s0 * NCLS + l]);
        if (l < 8) accB0 += w0 * __ldg(&g_H2[s0 * NCLS + 32 + l]);
    }

    float inv = 1.f / ((den0 + den1) + (den2 + den3));
    out[d * NCLS + l] = ((accA0 + accA1) + (accA2 + accA3)) * inv + b2[l];
    if (l < 8) out[d * NCLS + 32 + l] = ((accB0 + accB1) + (accB2 + accB3)) * inv + b2[32 + l];
}

// ---------------- launch ----------------
static cudaStream_t g_s2 = nullptr;
static cudaEvent_t g_evFork = nullptr, g_evJoin = nullptr, g_evA = nullptr, g_evG = nullptr;

extern "C" void kernel_launch(void* const* d_in, const int* in_sizes, int n_in,
                              void* d_out, int out_size) {
    const float* x   = (const float*)d_in[0];
    const int*   ei  = (const int*)d_in[1];     // int32 (JAX x64 disabled)
    const float* W1  = (const float*)d_in[2];
    const float* as1 = (const float*)d_in[3];
    const float* ad1 = (const float*)d_in[4];
    const float* b1  = (const float*)d_in[5];
    const float* W2  = (const float*)d_in[6];
    const float* as2 = (const float*)d_in[7];
    const float* ad2 = (const float*)d_in[8];
    const float* b2  = (const float*)d_in[9];
    float* out = (float*)d_out;

    if (g_s2 == nullptr) {
        cudaStreamCreateWithFlags(&g_s2, cudaStreamNonBlocking);
        cudaEventCreateWithFlags(&g_evFork, cudaEventDisableTiming);
        cudaEventCreateWithFlags(&g_evJoin, cudaEventDisableTiming);
        cudaEventCreateWithFlags(&g_evA, cudaEventDisableTiming);
        cudaEventCreateWithFlags(&g_evG, cudaEventDisableTiming);
        cudaFuncSetAttribute(gemm1_mma_kernel,
                             cudaFuncAttributeMaxDynamicSharedMemorySize, SM_WORDS * 4);
        cudaFuncSetAttribute(gemm2_mma_kernel,
                             cudaFuncAttributeMaxDynamicSharedMemorySize, SM2_WORDS * 4);
    }

    // fork: CSR build on side stream (g_deg is self-restoring; no zero pass)
    cudaEventRecord(g_evFork, 0);
    cudaStreamWaitEvent(g_s2, g_evFork, 0);

    count_kernel<<<(EE / 4 + 255) / 256, 256, 0, g_s2>>>(ei);
    blockscan_kernel<<<NBLK, 1024, 0, g_s2>>>();
    addoff_kernel<<<NBLK, 1024, 0, g_s2>>>();
    fill_kernel<<<(EE / 4 + 255) / 256, 256, 0, g_s2>>>(ei);
    cudaEventRecord(g_evJoin, g_s2);

    // main stream: tensor-core GEMM1 with fused attn1
    gemm1_mma_kernel<<<(NN + 127) / 128, 256, SM_WORDS * 4>>>(x, W1, as1, ad1);

    // join; then pipeline agg1 halves with gemm2 halves
    cudaStreamWaitEvent(0, g_evJoin, 0);
    agg1_kernel<<<(HALF0 * 32) / 256, 256>>>(b1, 0, HALF0);
    cudaEventRecord(g_evA, 0);
    agg1_kernel<<<(HALF1 * 32 + 255) / 256, 256>>>(b1, HALF0, HALF1);

    cudaStreamWaitEvent(g_s2, g_evA, 0);
    gemm2_mma_kernel<<<HALF0 / 128, 256, SM2_WORDS * 4, g_s2>>>(W2, as2, ad2, 0);
    cudaEventRecord(g_evG, g_s2);

    gemm2_mma_kernel<<<(NN + 127) / 128 - HALF0 / 128, 256, SM2_WORDS * 4>>>(W2, as2, ad2, HALF0 / 128);
    cudaStreamWaitEvent(0, g_evG, 0);
    agg2_kernel<<<(NN * 32 + 255) / 256, 256>>>(b2, out);
}

// round 13
// speedup vs baseline: 1.0610x; 1.0291x over previous
#include <cuda_runtime.h>
#include <cuda_bf16.h>
#include <cstdint>

#define NN 50000
#define EE 800000
#define NCLS 40
#define SLOT 128     // padded CSR slots per node; P(deg>128) ~ 1e-80
#define HALF0 25088  // 196 tiles of 128
#define HALF1 (NN - HALF0)

// ---------------- device scratch (static, allocation-free) ----------------
__device__ __align__(16) float g_H1[NN * 128];    // layer1 features (fp32)
__device__ __align__(16) float g_out1[NN * 128];  // layer1 output after ELU
__device__ __align__(16) float g_H2[NN * NCLS];   // layer2 features
__device__ __align__(16) float g_asrc1[NN * 8];
__device__ __align__(16) float g_adst1[NN * 8];
__device__ float g_asrc2[NN];
__device__ float g_adst2[NN];
__device__ int g_deg[NN];          // zeroed by agg2 each replay (starts zero)
__device__ int g_csr[NN * SLOT];   // padded CSR

__device__ __forceinline__ float lrelu(float x) { return x > 0.f ? x : 0.2f * x; }

// ---------------- CSR build: single pass into padded slots ----------------
__global__ void fill_kernel(const int* __restrict__ ei) {
    int q = blockIdx.x * blockDim.x + threadIdx.x;
    if (q < EE / 4) {
        int4 s4 = __ldg((const int4*)ei + q);
        int4 d4 = __ldg((const int4*)(ei + EE) + q);
        int p0 = atomicAdd(&g_deg[d4.x], 1);
        int p1 = atomicAdd(&g_deg[d4.y], 1);
        int p2 = atomicAdd(&g_deg[d4.z], 1);
        int p3 = atomicAdd(&g_deg[d4.w], 1);
        g_csr[(d4.x << 7) + p0] = s4.x;
        g_csr[(d4.y << 7) + p1] = s4.y;
        g_csr[(d4.z << 7) + p2] = s4.z;
        g_csr[(d4.w << 7) + p3] = s4.w;
    }
}

// ---------------- shared MMA helpers ----------------
__device__ __forceinline__ void mma_bf16(float* c, const uint32_t* a, uint32_t b0, uint32_t b1) {
    asm volatile(
        "mma.sync.aligned.m16n8k16.row.col.f32.bf16.bf16.f32 "
        "{%0,%1,%2,%3}, {%4,%5,%6,%7}, {%8,%9}, {%0,%1,%2,%3};"
        : "+f"(c[0]), "+f"(c[1]), "+f"(c[2]), "+f"(c[3])
        : "r"(a[0]), "r"(a[1]), "r"(a[2]), "r"(a[3]), "r"(b0), "r"(b1));
}

__device__ __forceinline__ uint32_t pack_bf2(float a, float b) {
    __nv_bfloat162 h = __floats2bfloat162_rn(a, b);
    return *(uint32_t*)&h;
}

// ---------------- GEMM1 via mma.sync bf16 (3-term hi/lo split) + fused attn1 ----
#define A_STRIDE 36
#define B_STRIDE 136
#define SM_AHI 0
#define SM_ALO (128 * A_STRIDE)
#define SM_BHI (2 * 128 * A_STRIDE)
#define SM_BLO (2 * 128 * A_STRIDE + 32 * B_STRIDE)
#define SM_WORDS (2 * 128 * A_STRIDE + 2 * 32 * B_STRIDE)

__global__ void __launch_bounds__(256, 1)
gemm1_mma_kernel(const float* __restrict__ x, const float* __restrict__ W1,
                 const float* __restrict__ as, const float* __restrict__ ad) {
    extern __shared__ uint32_t sm[];
    uint32_t* Ahi = sm + SM_AHI;
    uint32_t* Alo = sm + SM_ALO;
    uint32_t* Bhi = sm + SM_BHI;
    uint32_t* Blo = sm + SM_BLO;

    int t = threadIdx.x, wid = t >> 5, lane = t & 31;
    int wr = wid & 3, wc = wid >> 2;
    int nbase = blockIdx.x * 128;

    float c[2][8][4];
#pragma unroll
    for (int rs = 0; rs < 2; rs++)
#pragma unroll
        for (int nf = 0; nf < 8; nf++)
#pragma unroll
            for (int q = 0; q < 4; q++) c[rs][nf][q] = 0.f;

    for (int kc = 0; kc < 2; kc++) {
        if (kc) __syncthreads();
#pragma unroll
        for (int i = 0; i < 8; i++) {
            int idx = t + 256 * i;
            int r = idx >> 4, c4 = idx & 15;
            int node = nbase + r;
            float4 v = make_float4(0.f, 0.f, 0.f, 0.f);
            if (node < NN) v = ((const float4*)x)[node * 32 + kc * 16 + c4];
            uint32_t h0 = pack_bf2(v.x, v.y), h1 = pack_bf2(v.z, v.w);
            __nv_bfloat162 hh0 = *(__nv_bfloat162*)&h0;
            __nv_bfloat162 hh1 = *(__nv_bfloat162*)&h1;
            uint32_t l0 = pack_bf2(v.x - __bfloat162float(hh0.x), v.y - __bfloat162float(hh0.y));
            uint32_t l1 = pack_bf2(v.z - __bfloat162float(hh1.x), v.w - __bfloat162float(hh1.y));
            int w = r * A_STRIDE + c4 * 2;
            Ahi[w] = h0; Ahi[w + 1] = h1;
            Alo[w] = l0; Alo[w + 1] = l1;
        }
#pragma unroll
        for (int i = 0; i < 32; i++) {
            int idx = t + 256 * i;
            int k = idx >> 7, j = idx & 127;
            float w = W1[(kc * 64 + k) * 128 + j];
            __nv_bfloat16 hi = __float2bfloat16(w);
            __nv_bfloat16 lo = __float2bfloat16(w - __bfloat162float(hi));
            int word = (k >> 1) * B_STRIDE + j;
            ((__nv_bfloat16*)(Bhi + word))[k & 1] = hi;
            ((__nv_bfloat16*)(Blo + word))[k & 1] = lo;
        }
        __syncthreads();

#pragma unroll
        for (int kk = 0; kk < 4; kk++) {
            uint32_t ah[2][4], al[2][4];
#pragma unroll
            for (int rs = 0; rs < 2; rs++) {
                int row = wr * 32 + rs * 16 + (lane >> 2);
                int base = row * A_STRIDE + kk * 8 + (lane & 3);
                ah[rs][0] = Ahi[base];
                ah[rs][1] = Ahi[base + 8 * A_STRIDE];
                ah[rs][2] = Ahi[base + 4];
                ah[rs][3] = Ahi[base + 8 * A_STRIDE + 4];
                al[rs][0] = Alo[base];
                al[rs][1] = Alo[base + 8 * A_STRIDE];
                al[rs][2] = Alo[base + 4];
                al[rs][3] = Alo[base + 8 * A_STRIDE + 4];
            }
#pragma unroll
            for (int nf = 0; nf < 8; nf++) {
                int j = wc * 64 + nf * 8 + (lane >> 2);
                int bw = (kk * 8 + (lane & 3)) * B_STRIDE + j;
                uint32_t bh0 = Bhi[bw], bh1 = Bhi[bw + 4 * B_STRIDE];
                uint32_t bl0 = Blo[bw], bl1 = Blo[bw + 4 * B_STRIDE];
#pragma unroll
                for (int rs = 0; rs < 2; rs++) {
                    mma_bf16(c[rs][nf], ah[rs], bh0, bh1);
                    mma_bf16(c[rs][nf], ah[rs], bl0, bl1);
                    mma_bf16(c[rs][nf], al[rs], bh0, bh1);
                }
            }
        }
    }

#pragma unroll
    for (int rs = 0; rs < 2; rs++) {
#pragma unroll
        for (int hh = 0; hh < 2; hh++) {
            int row = wr * 32 + rs * 16 + (lane >> 2) + hh * 8;
            int node = nbase + row;
            float ss[4] = {0.f, 0.f, 0.f, 0.f};
            float dd[4] = {0.f, 0.f, 0.f, 0.f};
#pragma unroll
            for (int nf = 0; nf < 8; nf++) {
                float v0 = c[rs][nf][hh * 2];
                float v1 = c[rs][nf][hh * 2 + 1];
                int col = wc * 64 + nf * 8 + (lane & 3) * 2;
                if (node < NN)
                    *(float2*)&g_H1[node * 128 + col] = make_float2(v0, v1);
                int hp = nf >> 1;
                int wcol = (nf & 1) * 8 + (lane & 3) * 2;
                int hb = (wc * 4 + hp) * 16 + wcol;
                ss[hp] += v0 * __ldg(&as[hb]) + v1 * __ldg(&as[hb + 1]);
                dd[hp] += v0 * __ldg(&ad[hb]) + v1 * __ldg(&ad[hb + 1]);
            }
#pragma unroll
            for (int hp = 0; hp < 4; hp++) {
                ss[hp] += __shfl_xor_sync(0xffffffffu, ss[hp], 1);
                ss[hp] += __shfl_xor_sync(0xffffffffu, ss[hp], 2);
                dd[hp] += __shfl_xor_sync(0xffffffffu, dd[hp], 1);
                dd[hp] += __shfl_xor_sync(0xffffffffu, dd[hp], 2);
            }
            if ((lane & 3) == 0 && node < NN) {
#pragma unroll
                for (int hp = 0; hp < 4; hp++) {
                    g_asrc1[node * 8 + wc * 4 + hp] = ss[hp];
                    g_adst1[node * 8 + wc * 4 + hp] = dd[hp];
                }
            }
        }
    }
}

// ---------------- layer-1 aggregation: warp per dst, unroll 8 (MLP 8) ----------
__global__ void agg1_kernel(const float* __restrict__ b1, int base, int cnt) {
    int w = base + ((blockIdx.x * blockDim.x + threadIdx.x) >> 5);
    int l = threadIdx.x & 31;
    if (w >= base + cnt || w >= NN) return;
    int d = w;
    int start = d << 7;
    int end = start + __ldg(&g_deg[d]);
    int hl = l >> 2;

    float adh = __ldg(&g_adst1[d * 8 + hl]);
    float wself = __expf(lrelu(__ldg(&g_asrc1[d * 8 + hl]) + adh));

    float den0 = wself, den1 = 0.f, den2 = 0.f, den3 = 0.f;
    float4 acc0, acc1, acc2, acc3;
    {
        float4 v = __ldg(((const float4*)g_H1) + d * 32 + l);
        acc0.x = wself * v.x; acc0.y = wself * v.y;
        acc0.z = wself * v.z; acc0.w = wself * v.w;
        acc1 = make_float4(0.f, 0.f, 0.f, 0.f);
        acc2 = make_float4(0.f, 0.f, 0.f, 0.f);
        acc3 = make_float4(0.f, 0.f, 0.f, 0.f);
    }

    int e = start;
    for (; e + 7 < end; e += 8) {
        int s0 = __ldg(&g_csr[e]);
        int s1 = __ldg(&g_csr[e + 1]);
        int s2 = __ldg(&g_csr[e + 2]);
        int s3 = __ldg(&g_csr[e + 3]);
        int s4 = __ldg(&g_csr[e + 4]);
        int s5 = __ldg(&g_csr[e + 5]);
        int s6 = __ldg(&g_csr[e + 6]);
        int s7 = __ldg(&g_csr[e + 7]);
        float w0 = __expf(lrelu(__ldg(&g_asrc1[s0 * 8 + hl]) + adh));
        float w1 = __expf(lrelu(__ldg(&g_asrc1[s1 * 8 + hl]) + adh));
        float w2 = __expf(lrelu(__ldg(&g_asrc1[s2 * 8 + hl]) + adh));
        float w3 = __expf(lrelu(__ldg(&g_asrc1[s3 * 8 + hl]) + adh));
        float w4 = __expf(lrelu(__ldg(&g_asrc1[s4 * 8 + hl]) + adh));
        float w5 = __expf(lrelu(__ldg(&g_asrc1[s5 * 8 + hl]) + adh));
        float w6 = __expf(lrelu(__ldg(&g_asrc1[s6 * 8 + hl]) + adh));
        float w7 = __expf(lrelu(__ldg(&g_asrc1[s7 * 8 + hl]) + adh));
        float4 v0 = __ldg(((const float4*)g_H1) + s0 * 32 + l);
        float4 v1 = __ldg(((const float4*)g_H1) + s1 * 32 + l);
        float4 v2 = __ldg(((const float4*)g_H1) + s2 * 32 + l);
        float4 v3 = __ldg(((const float4*)g_H1) + s3 * 32 + l);
        float4 v4 = __ldg(((const float4*)g_H1) + s4 * 32 + l);
        float4 v5 = __ldg(((const float4*)g_H1) + s5 * 32 + l);
        float4 v6 = __ldg(((const float4*)g_H1) + s6 * 32 + l);
        float4 v7 = __ldg(((const float4*)g_H1) + s7 * 32 + l);
        den0 += w0 + w4; den1 += w1 + w5; den2 += w2 + w6; den3 += w3 + w7;
        acc0.x += w0 * v0.x + w4 * v4.x; acc0.y += w0 * v0.y + w4 * v4.y;
        acc0.z += w0 * v0.z + w4 * v4.z; acc0.w += w0 * v0.w + w4 * v4.w;
        acc1.x += w1 * v1.x + w5 * v5.x; acc1.y += w1 * v1.y + w5 * v5.y;
        acc1.z += w1 * v1.z + w5 * v5.z; acc1.w += w1 * v1.w + w5 * v5.w;
        acc2.x += w2 * v2.x + w6 * v6.x; acc2.y += w2 * v2.y + w6 * v6.y;
        acc2.z += w2 * v2.z + w6 * v6.z; acc2.w += w2 * v2.w + w6 * v6.w;
        acc3.x += w3 * v3.x + w7 * v7.x; acc3.y += w3 * v3.y + w7 * v7.y;
        acc3.z += w3 * v3.z + w7 * v7.z; acc3.w += w3 * v3.w + w7 * v7.w;
    }
    for (; e + 1 < end; e += 2) {
        int s0 = __ldg(&g_csr[e]);
        int s1 = __ldg(&g_csr[e + 1]);
        float w0 = __expf(lrelu(__ldg(&g_asrc1[s0 * 8 + hl]) + adh));
        float w1 = __expf(lrelu(__ldg(&g_asrc1[s1 * 8 + hl]) + adh));
        float4 v0 = __ldg(((const float4*)g_H1) + s0 * 32 + l);
        float4 v1 = __ldg(((const float4*)g_H1) + s1 * 32 + l);
        den0 += w0; den1 += w1;
        acc0.x += w0 * v0.x; acc0.y += w0 * v0.y; acc0.z += w0 * v0.z; acc0.w += w0 * v0.w;
        acc1.x += w1 * v1.x; acc1.y += w1 * v1.y; acc1.z += w1 * v1.z; acc1.w += w1 * v1.w;
    }
    if (e < end) {
        int s0 = __ldg(&g_csr[e]);
        float w0 = __expf(lrelu(__ldg(&g_asrc1[s0 * 8 + hl]) + adh));
        float4 v0 = __ldg(((const float4*)g_H1) + s0 * 32 + l);
        den0 += w0;
        acc0.x += w0 * v0.x; acc0.y += w0 * v0.y;
        acc0.z += w0 * v0.z; acc0.w += w0 * v0.w;
    }

    float inv = 1.f / ((den0 + den1) + (den2 + den3));
    float4 bb = ((const float4*)b1)[l];
    float4 r;
    r.x = ((acc0.x + acc1.x) + (acc2.x + acc3.x)) * inv + bb.x;
    r.y = ((acc0.y + acc1.y) + (acc2.y + acc3.y)) * inv + bb.y;
    r.z = ((acc0.z + acc1.z) + (acc2.z + acc3.z)) * inv + bb.z;
    r.w = ((acc0.w + acc1.w) + (acc2.w + acc3.w)) * inv + bb.w;
    r.x = r.x > 0.f ? r.x : __expf(r.x) - 1.f;
    r.y = r.y > 0.f ? r.y : __expf(r.y) - 1.f;
    r.z = r.z > 0.f ? r.z : __expf(r.z) - 1.f;
    r.w = r.w > 0.f ? r.w : __expf(r.w) - 1.f;
    ((float4*)g_out1)[d * 32 + l] = r;
}

// ---------------- GEMM2 via mma.sync bf16 split + fused attn2 (tile offset) ----
#define A2_STRIDE 68
#define B2_STRIDE 44
#define SM2_ALO (128 * A2_STRIDE)
#define SM2_BHI (2 * 128 * A2_STRIDE)
#define SM2_BLO (2 * 128 * A2_STRIDE + 64 * B2_STRIDE)
#define SM2_WORDS (2 * 128 * A2_STRIDE + 2 * 64 * B2_STRIDE)

__global__ void __launch_bounds__(256, 1)
gemm2_mma_kernel(const float* __restrict__ W2,
                 const float* __restrict__ as2, const float* __restrict__ ad2,
                 int tile0) {
    extern __shared__ uint32_t sm[];
    uint32_t* Ahi = sm;
    uint32_t* Alo = sm + SM2_ALO;
    uint32_t* Bhi = sm + SM2_BHI;
    uint32_t* Blo = sm + SM2_BLO;

    int t = threadIdx.x, wid = t >> 5, lane = t & 31;
    int nbase = (tile0 + blockIdx.x) * 128;

#pragma unroll
    for (int i = 0; i < 16; i++) {
        int idx = t + 256 * i;
        int r = idx >> 5, c4 = idx & 31;
        int node = nbase + r;
        float4 v = make_float4(0.f, 0.f, 0.f, 0.f);
        if (node < NN) v = ((const float4*)g_out1)[node * 32 + c4];
        uint32_t h0 = pack_bf2(v.x, v.y), h1 = pack_bf2(v.z, v.w);
        __nv_bfloat162 hh0 = *(__nv_bfloat162*)&h0;
        __nv_bfloat162 hh1 = *(__nv_bfloat162*)&h1;
        uint32_t l0 = pack_bf2(v.x - __bfloat162float(hh0.x), v.y - __bfloat162float(hh0.y));
        uint32_t l1 = pack_bf2(v.z - __bfloat162float(hh1.x), v.w - __bfloat162float(hh1.y));
        int w = r * A2_STRIDE + c4 * 2;
        Ahi[w] = h0; Ahi[w + 1] = h1;
        Alo[w] = l0; Alo[w + 1] = l1;
    }
    for (int idx = t; idx < 128 * NCLS; idx += 256) {
        int k = idx / NCLS, j = idx % NCLS;
        float w = W2[idx];
        __nv_bfloat16 hi = __float2bfloat16(w);
        __nv_bfloat16 lo = __float2bfloat16(w - __bfloat162float(hi));
        int word = (k >> 1) * B2_STRIDE + j;
        ((__nv_bfloat16*)(Bhi + word))[k & 1] = hi;
        ((__nv_bfloat16*)(Blo + word))[k & 1] = lo;
    }
    __syncthreads();

    float c[5][4];
#pragma unroll
    for (int nf = 0; nf < 5; nf++)
#pragma unroll
        for (int q = 0; q < 4; q++) c[nf][q] = 0.f;

#pragma unroll
    for (int kk = 0; kk < 8; kk++) {
        int base = (wid * 16 + (lane >> 2)) * A2_STRIDE + kk * 8 + (lane & 3);
        uint32_t ah[4], al[4];
        ah[0] = Ahi[base];
        ah[1] = Ahi[base + 8 * A2_STRIDE];
        ah[2] = Ahi[base + 4];
        ah[3] = Ahi[base + 8 * A2_STRIDE + 4];
        al[0] = Alo[base];
        al[1] = Alo[base + 8 * A2_STRIDE];
        al[2] = Alo[base + 4];
        al[3] = Alo[base + 8 * A2_STRIDE + 4];
#pragma unroll
        for (int nf = 0; nf < 5; nf++) {
            int j = nf * 8 + (lane >> 2);
            int bw = (kk * 8 + (lane & 3)) * B2_STRIDE + j;
            uint32_t bh0 = Bhi[bw], bh1 = Bhi[bw + 4 * B2_STRIDE];
            uint32_t bl0 = Blo[bw], bl1 = Blo[bw + 4 * B2_STRIDE];
            mma_bf16(c[nf], ah, bh0, bh1);
            mma_bf16(c[nf], ah, bl0, bl1);
            mma_bf16(c[nf], al, bh0, bh1);
        }
    }

#pragma unroll
    for (int hh = 0; hh < 2; hh++) {
        int row = wid * 16 + (lane >> 2) + hh * 8;
        int node = nbase + row;
        float ps = 0.f, pd = 0.f;
#pragma unroll
        for (int nf = 0; nf < 5; nf++) {
            float v0 = c[nf][hh * 2];
            float v1 = c[nf][hh * 2 + 1];
            int col = nf * 8 + (lane & 3) * 2;
            if (node < NN)
                *(float2*)&g_H2[node * NCLS + col] = make_float2(v0, v1);
            ps += v0 * __ldg(&as2[col]) + v1 * __ldg(&as2[col + 1]);
            pd += v0 * __ldg(&ad2[col]) + v1 * __ldg(&ad2[col + 1]);
        }
        ps += __shfl_xor_sync(0xffffffffu, ps, 1);
        ps += __shfl_xor_sync(0xffffffffu, ps, 2);
        pd += __shfl_xor_sync(0xffffffffu, pd, 1);
        pd += __shfl_xor_sync(0xffffffffu, pd, 2);
        if ((lane & 3) == 0 && node < NN) {
            g_asrc2[node] = ps;
            g_adst2[node] = pd;
        }
    }
}

// ---------------- layer-2 aggregation: warp per dst; resets g_deg ----------------
__global__ void agg2_kernel(const float* __restrict__ b2, float* __restrict__ out) {
    int w = (blockIdx.x * blockDim.x + threadIdx.x) >> 5;
    int l = threadIdx.x & 31;
    if (w >= NN) return;
    int d = w;
    int start = d << 7;
    int deg = __ldg(&g_deg[d]);
    int end = start + deg;

    float adst = __ldg(&g_adst2[d]);
    float wself = __expf(lrelu(__ldg(&g_asrc2[d]) + adst));

    float den0 = wself, den1 = 0.f, den2 = 0.f, den3 = 0.f;
    float accA0 = wself * __ldg(&g_H2[d * NCLS + l]);
    float accA1 = 0.f, accA2 = 0.f, accA3 = 0.f;
    float accB0 = (l < 8) ? wself * __ldg(&g_H2[d * NCLS + 32 + l]) : 0.f;
    float accB1 = 0.f, accB2 = 0.f, accB3 = 0.f;

    int e = start;
    for (; e + 3 < end; e += 4) {
        int s0 = __ldg(&g_csr[e]);
        int s1 = __ldg(&g_csr[e + 1]);
        int s2 = __ldg(&g_csr[e + 2]);
        int s3 = __ldg(&g_csr[e + 3]);
        float w0 = __expf(lrelu(__ldg(&g_asrc2[s0]) + adst));
        float w1 = __expf(lrelu(__ldg(&g_asrc2[s1]) + adst));
        float w2 = __expf(lrelu(__ldg(&g_asrc2[s2]) + adst));
        float w3 = __expf(lrelu(__ldg(&g_asrc2[s3]) + adst));
        den0 += w0; den1 += w1; den2 += w2; den3 += w3;
        accA0 += w0 * __ldg(&g_H2[s0 * NCLS + l]);
        accA1 += w1 * __ldg(&g_H2[s1 * NCLS + l]);
        accA2 += w2 * __ldg(&g_H2[s2 * NCLS + l]);
        accA3 += w3 * __ldg(&g_H2[s3 * NCLS + l]);
        if (l < 8) {
            accB0 += w0 * __ldg(&g_H2[s0 * NCLS + 32 + l]);
            accB1 += w1 * __ldg(&g_H2[s1 * NCLS + 32 + l]);
            accB2 += w2 * __ldg(&g_H2[s2 * NCLS + 32 + l]);
            accB3 += w3 * __ldg(&g_H2[s3 * NCLS + 32 + l]);
        }
    }
    for (; e < end; e++) {
        int s0 = __ldg(&g_csr[e]);
        float w0 = __expf(lrelu(__ldg(&g_asrc2[s0]) + adst));
        den0 += w0;
        accA0 += w0 * __ldg(&g_H2[s0 * NCLS + l]);
        if (l < 8) accB0 += w0 * __ldg(&g_H2[s0 * NCLS + 32 + l]);
    }

    float inv = 1.f / ((den0 + den1) + (den2 + den3));
    out[d * NCLS + l] = ((accA0 + accA1) + (accA2 + accA3)) * inv + b2[l];
    if (l < 8) out[d * NCLS + 32 + l] = ((accB0 + accB1) + (accB2 + accB3)) * inv + b2[32 + l];
    if (l == 0) g_deg[d] = 0;   // restore invariant for next replay
}

// ---------------- launch ----------------
static cudaStream_t g_s2 = nullptr;
static cudaEvent_t g_evFork = nullptr, g_evJoin = nullptr, g_evA = nullptr, g_evG = nullptr;

extern "C" void kernel_launch(void* const* d_in, const int* in_sizes, int n_in,
                              void* d_out, int out_size) {
    const float* x   = (const float*)d_in[0];
    const int*   ei  = (const int*)d_in[1];     // int32 (JAX x64 disabled)
    const float* W1  = (const float*)d_in[2];
    const float* as1 = (const float*)d_in[3];
    const float* ad1 = (const float*)d_in[4];
    const float* b1  = (const float*)d_in[5];
    const float* W2  = (const float*)d_in[6];
    const float* as2 = (const float*)d_in[7];
    const float* ad2 = (const float*)d_in[8];
    const float* b2  = (const float*)d_in[9];
    float* out = (float*)d_out;

    if (g_s2 == nullptr) {
        cudaStreamCreateWithFlags(&g_s2, cudaStreamNonBlocking);
        cudaEventCreateWithFlags(&g_evFork, cudaEventDisableTiming);
        cudaEventCreateWithFlags(&g_evJoin, cudaEventDisableTiming);
        cudaEventCreateWithFlags(&g_evA, cudaEventDisableTiming);
        cudaEventCreateWithFlags(&g_evG, cudaEventDisableTiming);
        cudaFuncSetAttribute(gemm1_mma_kernel,
                             cudaFuncAttributeMaxDynamicSharedMemorySize, SM_WORDS * 4);
        cudaFuncSetAttribute(gemm2_mma_kernel,
                             cudaFuncAttributeMaxDynamicSharedMemorySize, SM2_WORDS * 4);
    }

    // fork: single-pass padded-CSR fill on side stream (g_deg zeroed by agg2)
    cudaEventRecord(g_evFork, 0);
    cudaStreamWaitEvent(g_s2, g_evFork, 0);
    fill_kernel<<<(EE / 4 + 255) / 256, 256, 0, g_s2>>>(ei);
    cudaEventRecord(g_evJoin, g_s2);

    // main stream: tensor-core GEMM1 with fused attn1
    gemm1_mma_kernel<<<(NN + 127) / 128, 256, SM_WORDS * 4>>>(x, W1, as1, ad1);

    // join; then pipeline agg1 halves with gemm2 halves
    cudaStreamWaitEvent(0, g_evJoin, 0);
    agg1_kernel<<<(HALF0 * 32) / 256, 256>>>(b1, 0, HALF0);
    cudaEventRecord(g_evA, 0);
    agg1_kernel<<<(HALF1 * 32 + 255) / 256, 256>>>(b1, HALF0, HALF1);

    cudaStreamWaitEvent(g_s2, g_evA, 0);
    gemm2_mma_kernel<<<HALF0 / 128, 256, SM2_WORDS * 4, g_s2>>>(W2, as2, ad2, 0);
    cudaEventRecord(g_evG, g_s2);

    gemm2_mma_kernel<<<(NN + 127) / 128 - HALF0 / 128, 256, SM2_WORDS * 4>>>(W2, as2, ad2, HALF0 / 128);
    cudaStreamWaitEvent(0, g_evG, 0);
    agg2_kernel<<<(NN * 32 + 255) / 256, 256>>>(b2, out);
}

// round 14
// speedup vs baseline: 1.0726x; 1.0109x over previous
#include <cuda_runtime.h>
#include <cuda_bf16.h>
#include <cstdint>

#define NN 50000
#define EE 800000
#define NCLS 40
#define SLOT 128     // padded CSR slots per node; P(deg>128) ~ 1e-80
#define HALF0 25088  // 196 tiles of 128
#define HALF1 (NN - HALF0)

// ---------------- device scratch (static, allocation-free) ----------------
__device__ __align__(16) float g_H1[NN * 128];    // layer1 features (fp32)
__device__ __align__(16) float g_out1[NN * 128];  // layer1 output after ELU
__device__ __align__(16) float g_H2[NN * NCLS];   // layer2 features
__device__ __align__(16) float g_asrc1[NN * 8];
__device__ __align__(16) float g_adst1[NN * 8];
__device__ float g_asrc2[NN];
__device__ float g_adst2[NN];
__device__ int g_deg[NN];          // zeroed by agg2 each replay (starts zero)
__device__ int g_csr[NN * SLOT];   // padded CSR

__device__ __forceinline__ float lrelu(float x) { return fmaxf(x, 0.2f * x); }

// ---------------- CSR build: single pass into padded slots ----------------
__global__ void fill_kernel(const int* __restrict__ ei) {
    int q = blockIdx.x * blockDim.x + threadIdx.x;
    if (q < EE / 4) {
        int4 s4 = __ldg((const int4*)ei + q);
        int4 d4 = __ldg((const int4*)(ei + EE) + q);
        int p0 = atomicAdd(&g_deg[d4.x], 1);
        int p1 = atomicAdd(&g_deg[d4.y], 1);
        int p2 = atomicAdd(&g_deg[d4.z], 1);
        int p3 = atomicAdd(&g_deg[d4.w], 1);
        g_csr[(d4.x << 7) + p0] = s4.x;
        g_csr[(d4.y << 7) + p1] = s4.y;
        g_csr[(d4.z << 7) + p2] = s4.z;
        g_csr[(d4.w << 7) + p3] = s4.w;
    }
}

// ---------------- shared MMA helpers ----------------
__device__ __forceinline__ void mma_bf16(float* c, const uint32_t* a, uint32_t b0, uint32_t b1) {
    asm volatile(
        "mma.sync.aligned.m16n8k16.row.col.f32.bf16.bf16.f32 "
        "{%0,%1,%2,%3}, {%4,%5,%6,%7}, {%8,%9}, {%0,%1,%2,%3};"
        : "+f"(c[0]), "+f"(c[1]), "+f"(c[2]), "+f"(c[3])
        : "r"(a[0]), "r"(a[1]), "r"(a[2]), "r"(a[3]), "r"(b0), "r"(b1));
}

__device__ __forceinline__ uint32_t pack_bf2(float a, float b) {
    __nv_bfloat162 h = __floats2bfloat162_rn(a, b);
    return *(uint32_t*)&h;
}

// ---------------- GEMM1 via mma.sync bf16 (3-term hi/lo split) + fused attn1 ----
#define A_STRIDE 36
#define B_STRIDE 136
#define SM_AHI 0
#define SM_ALO (128 * A_STRIDE)
#define SM_BHI (2 * 128 * A_STRIDE)
#define SM_BLO (2 * 128 * A_STRIDE + 32 * B_STRIDE)
#define SM_WORDS (2 * 128 * A_STRIDE + 2 * 32 * B_STRIDE)

__global__ void __launch_bounds__(256, 2)
gemm1_mma_kernel(const float* __restrict__ x, const float* __restrict__ W1,
                 const float* __restrict__ as, const float* __restrict__ ad) {
    extern __shared__ uint32_t sm[];
    uint32_t* Ahi = sm + SM_AHI;
    uint32_t* Alo = sm + SM_ALO;
    uint32_t* Bhi = sm + SM_BHI;
    uint32_t* Blo = sm + SM_BLO;

    int t = threadIdx.x, wid = t >> 5, lane = t & 31;
    int wr = wid & 3, wc = wid >> 2;
    int nbase = blockIdx.x * 128;

    float c[2][8][4];
#pragma unroll
    for (int rs = 0; rs < 2; rs++)
#pragma unroll
        for (int nf = 0; nf < 8; nf++)
#pragma unroll
            for (int q = 0; q < 4; q++) c[rs][nf][q] = 0.f;

    for (int kc = 0; kc < 2; kc++) {
        if (kc) __syncthreads();
#pragma unroll
        for (int i = 0; i < 8; i++) {
            int idx = t + 256 * i;
            int r = idx >> 4, c4 = idx & 15;
            int node = nbase + r;
            float4 v = make_float4(0.f, 0.f, 0.f, 0.f);
            if (node < NN) v = ((const float4*)x)[node * 32 + kc * 16 + c4];
            uint32_t h0 = pack_bf2(v.x, v.y), h1 = pack_bf2(v.z, v.w);
            __nv_bfloat162 hh0 = *(__nv_bfloat162*)&h0;
            __nv_bfloat162 hh1 = *(__nv_bfloat162*)&h1;
            uint32_t l0 = pack_bf2(v.x - __bfloat162float(hh0.x), v.y - __bfloat162float(hh0.y));
            uint32_t l1 = pack_bf2(v.z - __bfloat162float(hh1.x), v.w - __bfloat162float(hh1.y));
            int w = r * A_STRIDE + c4 * 2;
            Ahi[w] = h0; Ahi[w + 1] = h1;
            Alo[w] = l0; Alo[w + 1] = l1;
        }
#pragma unroll
        for (int i = 0; i < 32; i++) {
            int idx = t + 256 * i;
            int k = idx >> 7, j = idx & 127;
            float w = W1[(kc * 64 + k) * 128 + j];
            __nv_bfloat16 hi = __float2bfloat16(w);
            __nv_bfloat16 lo = __float2bfloat16(w - __bfloat162float(hi));
            int word = (k >> 1) * B_STRIDE + j;
            ((__nv_bfloat16*)(Bhi + word))[k & 1] = hi;
            ((__nv_bfloat16*)(Blo + word))[k & 1] = lo;
        }
        __syncthreads();

#pragma unroll
        for (int kk = 0; kk < 4; kk++) {
            uint32_t ah[2][4], al[2][4];
#pragma unroll
            for (int rs = 0; rs < 2; rs++) {
                int row = wr * 32 + rs * 16 + (lane >> 2);
                int base = row * A_STRIDE + kk * 8 + (lane & 3);
                ah[rs][0] = Ahi[base];
                ah[rs][1] = Ahi[base + 8 * A_STRIDE];
                ah[rs][2] = Ahi[base + 4];
                ah[rs][3] = Ahi[base + 8 * A_STRIDE + 4];
                al[rs][0] = Alo[base];
                al[rs][1] = Alo[base + 8 * A_STRIDE];
                al[rs][2] = Alo[base + 4];
                al[rs][3] = Alo[base + 8 * A_STRIDE + 4];
            }
#pragma unroll
            for (int nf = 0; nf < 8; nf++) {
                int j = wc * 64 + nf * 8 + (lane >> 2);
                int bw = (kk * 8 + (lane & 3)) * B_STRIDE + j;
                uint32_t bh0 = Bhi[bw], bh1 = Bhi[bw + 4 * B_STRIDE];
                uint32_t bl0 = Blo[bw], bl1 = Blo[bw + 4 * B_STRIDE];
#pragma unroll
                for (int rs = 0; rs < 2; rs++) {
                    mma_bf16(c[rs][nf], ah[rs], bh0, bh1);
                    mma_bf16(c[rs][nf], ah[rs], bl0, bl1);
                    mma_bf16(c[rs][nf], al[rs], bh0, bh1);
                }
            }
        }
    }

#pragma unroll
    for (int rs = 0; rs < 2; rs++) {
#pragma unroll
        for (int hh = 0; hh < 2; hh++) {
            int row = wr * 32 + rs * 16 + (lane >> 2) + hh * 8;
            int node = nbase + row;
            float ss[4] = {0.f, 0.f, 0.f, 0.f};
            float dd[4] = {0.f, 0.f, 0.f, 0.f};
#pragma unroll
            for (int nf = 0; nf < 8; nf++) {
                float v0 = c[rs][nf][hh * 2];
                float v1 = c[rs][nf][hh * 2 + 1];
                int col = wc * 64 + nf * 8 + (lane & 3) * 2;
                if (node < NN)
                    *(float2*)&g_H1[node * 128 + col] = make_float2(v0, v1);
                int hp = nf >> 1;
                int wcol = (nf & 1) * 8 + (lane & 3) * 2;
                int hb = (wc * 4 + hp) * 16 + wcol;
                ss[hp] += v0 * __ldg(&as[hb]) + v1 * __ldg(&as[hb + 1]);
                dd[hp] += v0 * __ldg(&ad[hb]) + v1 * __ldg(&ad[hb + 1]);
            }
#pragma unroll
            for (int hp = 0; hp < 4; hp++) {
                ss[hp] += __shfl_xor_sync(0xffffffffu, ss[hp], 1);
                ss[hp] += __shfl_xor_sync(0xffffffffu, ss[hp], 2);
                dd[hp] += __shfl_xor_sync(0xffffffffu, dd[hp], 1);
                dd[hp] += __shfl_xor_sync(0xffffffffu, dd[hp], 2);
            }
            if ((lane & 3) == 0 && node < NN) {
#pragma unroll
                for (int hp = 0; hp < 4; hp++) {
                    g_asrc1[node * 8 + wc * 4 + hp] = ss[hp];
                    g_adst1[node * 8 + wc * 4 + hp] = dd[hp];
                }
            }
        }
    }
}

// ---------------- layer-1 aggregation: warp per dst, unroll 8, occ-boosted ------
__global__ void __launch_bounds__(256, 5)
agg1_kernel(const float* __restrict__ b1, int base, int cnt) {
    int w = base + ((blockIdx.x * blockDim.x + threadIdx.x) >> 5);
    int l = threadIdx.x & 31;
    if (w >= base + cnt || w >= NN) return;
    int d = w;
    int start = d << 7;
    int end = start + __ldg(&g_deg[d]);
    int hl = l >> 2;

    float adh = __ldg(&g_adst1[d * 8 + hl]);
    float wself = __expf(lrelu(__ldg(&g_asrc1[d * 8 + hl]) + adh));

    float den0 = wself, den1 = 0.f, den2 = 0.f, den3 = 0.f;
    float4 acc0, acc1, acc2, acc3;
    {
        float4 v = __ldg(((const float4*)g_H1) + d * 32 + l);
        acc0.x = wself * v.x; acc0.y = wself * v.y;
        acc0.z = wself * v.z; acc0.w = wself * v.w;
        acc1 = make_float4(0.f, 0.f, 0.f, 0.f);
        acc2 = make_float4(0.f, 0.f, 0.f, 0.f);
        acc3 = make_float4(0.f, 0.f, 0.f, 0.f);
    }

    int e = start;
    for (; e + 7 < end; e += 8) {
        int s0 = __ldg(&g_csr[e]);
        int s1 = __ldg(&g_csr[e + 1]);
        int s2 = __ldg(&g_csr[e + 2]);
        int s3 = __ldg(&g_csr[e + 3]);
        int s4 = __ldg(&g_csr[e + 4]);
        int s5 = __ldg(&g_csr[e + 5]);
        int s6 = __ldg(&g_csr[e + 6]);
        int s7 = __ldg(&g_csr[e + 7]);
        float w0 = __expf(lrelu(__ldg(&g_asrc1[s0 * 8 + hl]) + adh));
        float w1 = __expf(lrelu(__ldg(&g_asrc1[s1 * 8 + hl]) + adh));
        float w2 = __expf(lrelu(__ldg(&g_asrc1[s2 * 8 + hl]) + adh));
        float w3 = __expf(lrelu(__ldg(&g_asrc1[s3 * 8 + hl]) + adh));
        float w4 = __expf(lrelu(__ldg(&g_asrc1[s4 * 8 + hl]) + adh));
        float w5 = __expf(lrelu(__ldg(&g_asrc1[s5 * 8 + hl]) + adh));
        float w6 = __expf(lrelu(__ldg(&g_asrc1[s6 * 8 + hl]) + adh));
        float w7 = __expf(lrelu(__ldg(&g_asrc1[s7 * 8 + hl]) + adh));
        float4 v0 = __ldg(((const float4*)g_H1) + s0 * 32 + l);
        float4 v1 = __ldg(((const float4*)g_H1) + s1 * 32 + l);
        float4 v2 = __ldg(((const float4*)g_H1) + s2 * 32 + l);
        float4 v3 = __ldg(((const float4*)g_H1) + s3 * 32 + l);
        float4 v4 = __ldg(((const float4*)g_H1) + s4 * 32 + l);
        float4 v5 = __ldg(((const float4*)g_H1) + s5 * 32 + l);
        float4 v6 = __ldg(((const float4*)g_H1) + s6 * 32 + l);
        float4 v7 = __ldg(((const float4*)g_H1) + s7 * 32 + l);
        den0 += w0 + w4; den1 += w1 + w5; den2 += w2 + w6; den3 += w3 + w7;
        acc0.x += w0 * v0.x + w4 * v4.x; acc0.y += w0 * v0.y + w4 * v4.y;
        acc0.z += w0 * v0.z + w4 * v4.z; acc0.w += w0 * v0.w + w4 * v4.w;
        acc1.x += w1 * v1.x + w5 * v5.x; acc1.y += w1 * v1.y + w5 * v5.y;
        acc1.z += w1 * v1.z + w5 * v5.z; acc1.w += w1 * v1.w + w5 * v5.w;
        acc2.x += w2 * v2.x + w6 * v6.x; acc2.y += w2 * v2.y + w6 * v6.y;
        acc2.z += w2 * v2.z + w6 * v6.z; acc2.w += w2 * v2.w + w6 * v6.w;
        acc3.x += w3 * v3.x + w7 * v7.x; acc3.y += w3 * v3.y + w7 * v7.y;
        acc3.z += w3 * v3.z + w7 * v7.z; acc3.w += w3 * v3.w + w7 * v7.w;
    }
    for (; e + 1 < end; e += 2) {
        int s0 = __ldg(&g_csr[e]);
        int s1 = __ldg(&g_csr[e + 1]);
        float w0 = __expf(lrelu(__ldg(&g_asrc1[s0 * 8 + hl]) + adh));
        float w1 = __expf(lrelu(__ldg(&g_asrc1[s1 * 8 + hl]) + adh));
        float4 v0 = __ldg(((const float4*)g_H1) + s0 * 32 + l);
        float4 v1 = __ldg(((const float4*)g_H1) + s1 * 32 + l);
        den0 += w0; den1 += w1;
        acc0.x += w0 * v0.x; acc0.y += w0 * v0.y; acc0.z += w0 * v0.z; acc0.w += w0 * v0.w;
        acc1.x += w1 * v1.x; acc1.y += w1 * v1.y; acc1.z += w1 * v1.z; acc1.w += w1 * v1.w;
    }
    if (e < end) {
        int s0 = __ldg(&g_csr[e]);
        float w0 = __expf(lrelu(__ldg(&g_asrc1[s0 * 8 + hl]) + adh));
        float4 v0 = __ldg(((const float4*)g_H1) + s0 * 32 + l);
        den0 += w0;
        acc0.x += w0 * v0.x; acc0.y += w0 * v0.y;
        acc0.z += w0 * v0.z; acc0.w += w0 * v0.w;
    }

    float inv = 1.f / ((den0 + den1) + (den2 + den3));
    float4 bb = ((const float4*)b1)[l];
    float4 r;
    r.x = ((acc0.x + acc1.x) + (acc2.x + acc3.x)) * inv + bb.x;
    r.y = ((acc0.y + acc1.y) + (acc2.y + acc3.y)) * inv + bb.y;
    r.z = ((acc0.z + acc1.z) + (acc2.z + acc3.z)) * inv + bb.z;
    r.w = ((acc0.w + acc1.w) + (acc2.w + acc3.w)) * inv + bb.w;
    r.x = r.x > 0.f ? r.x : __expf(r.x) - 1.f;
    r.y = r.y > 0.f ? r.y : __expf(r.y) - 1.f;
    r.z = r.z > 0.f ? r.z : __expf(r.z) - 1.f;
    r.w = r.w > 0.f ? r.w : __expf(r.w) - 1.f;
    ((float4*)g_out1)[d * 32 + l] = r;
}

// ---------------- GEMM2 via mma.sync bf16 split + fused attn2 (tile offset) ----
#define A2_STRIDE 68
#define B2_STRIDE 44
#define SM2_ALO (128 * A2_STRIDE)
#define SM2_BHI (2 * 128 * A2_STRIDE)
#define SM2_BLO (2 * 128 * A2_STRIDE + 64 * B2_STRIDE)
#define SM2_WORDS (2 * 128 * A2_STRIDE + 2 * 64 * B2_STRIDE)

__global__ void __launch_bounds__(256, 2)
gemm2_mma_kernel(const float* __restrict__ W2,
                 const float* __restrict__ as2, const float* __restrict__ ad2,
                 int tile0) {
    extern __shared__ uint32_t sm[];
    uint32_t* Ahi = sm;
    uint32_t* Alo = sm + SM2_ALO;
    uint32_t* Bhi = sm + SM2_BHI;
    uint32_t* Blo = sm + SM2_BLO;

    int t = threadIdx.x, wid = t >> 5, lane = t & 31;
    int nbase = (tile0 + blockIdx.x) * 128;

#pragma unroll
    for (int i = 0; i < 16; i++) {
        int idx = t + 256 * i;
        int r = idx >> 5, c4 = idx & 31;
        int node = nbase + r;
        float4 v = make_float4(0.f, 0.f, 0.f, 0.f);
        if (node < NN) v = ((const float4*)g_out1)[node * 32 + c4];
        uint32_t h0 = pack_bf2(v.x, v.y), h1 = pack_bf2(v.z, v.w);
        __nv_bfloat162 hh0 = *(__nv_bfloat162*)&h0;
        __nv_bfloat162 hh1 = *(__nv_bfloat162*)&h1;
        uint32_t l0 = pack_bf2(v.x - __bfloat162float(hh0.x), v.y - __bfloat162float(hh0.y));
        uint32_t l1 = pack_bf2(v.z - __bfloat162float(hh1.x), v.w - __bfloat162float(hh1.y));
        int w = r * A2_STRIDE + c4 * 2;
        Ahi[w] = h0; Ahi[w + 1] = h1;
        Alo[w] = l0; Alo[w + 1] = l1;
    }
    for (int idx = t; idx < 128 * NCLS; idx += 256) {
        int k = idx / NCLS, j = idx % NCLS;
        float w = W2[idx];
        __nv_bfloat16 hi = __float2bfloat16(w);
        __nv_bfloat16 lo = __float2bfloat16(w - __bfloat162float(hi));
        int word = (k >> 1) * B2_STRIDE + j;
        ((__nv_bfloat16*)(Bhi + word))[k & 1] = hi;
        ((__nv_bfloat16*)(Blo + word))[k & 1] = lo;
    }
    __syncthreads();

    float c[5][4];
#pragma unroll
    for (int nf = 0; nf < 5; nf++)
#pragma unroll
        for (int q = 0; q < 4; q++) c[nf][q] = 0.f;

#pragma unroll
    for (int kk = 0; kk < 8; kk++) {
        int base = (wid * 16 + (lane >> 2)) * A2_STRIDE + kk * 8 + (lane & 3);
        uint32_t ah[4], al[4];
        ah[0] = Ahi[base];
        ah[1] = Ahi[base + 8 * A2_STRIDE];
        ah[2] = Ahi[base + 4];
        ah[3] = Ahi[base + 8 * A2_STRIDE + 4];
        al[0] = Alo[base];
        al[1] = Alo[base + 8 * A2_STRIDE];
        al[2] = Alo[base + 4];
        al[3] = Alo[base + 8 * A2_STRIDE + 4];
#pragma unroll
        for (int nf = 0; nf < 5; nf++) {
            int j = nf * 8 + (lane >> 2);
            int bw = (kk * 8 + (lane & 3)) * B2_STRIDE + j;
            uint32_t bh0 = Bhi[bw], bh1 = Bhi[bw + 4 * B2_STRIDE];
            uint32_t bl0 = Blo[bw], bl1 = Blo[bw + 4 * B2_STRIDE];
            mma_bf16(c[nf], ah, bh0, bh1);
            mma_bf16(c[nf], ah, bl0, bl1);
            mma_bf16(c[nf], al, bh0, bh1);
        }
    }

#pragma unroll
    for (int hh = 0; hh < 2; hh++) {
        int row = wid * 16 + (lane >> 2) + hh * 8;
        int node = nbase + row;
        float ps = 0.f, pd = 0.f;
#pragma unroll
        for (int nf = 0; nf < 5; nf++) {
            float v0 = c[nf][hh * 2];
            float v1 = c[nf][hh * 2 + 1];
            int col = nf * 8 + (lane & 3) * 2;
            if (node < NN)
                *(float2*)&g_H2[node * NCLS + col] = make_float2(v0, v1);
            ps += v0 * __ldg(&as2[col]) + v1 * __ldg(&as2[col + 1]);
            pd += v0 * __ldg(&ad2[col]) + v1 * __ldg(&ad2[col + 1]);
        }
        ps += __shfl_xor_sync(0xffffffffu, ps, 1);
        ps += __shfl_xor_sync(0xffffffffu, ps, 2);
        pd += __shfl_xor_sync(0xffffffffu, pd, 1);
        pd += __shfl_xor_sync(0xffffffffu, pd, 2);
        if ((lane & 3) == 0 && node < NN) {
            g_asrc2[node] = ps;
            g_adst2[node] = pd;
        }
    }
}

// ---------------- layer-2 aggregation: warp per dst; resets g_deg ----------------
__global__ void __launch_bounds__(256, 5)
agg2_kernel(const float* __restrict__ b2, float* __restrict__ out) {
    int w = (blockIdx.x * blockDim.x + threadIdx.x) >> 5;
    int l = threadIdx.x & 31;
    if (w >= NN) return;
    int d = w;
    int start = d << 7;
    int deg = __ldg(&g_deg[d]);
    int end = start + deg;

    float adst = __ldg(&g_adst2[d]);
    float wself = __expf(lrelu(__ldg(&g_asrc2[d]) + adst));

    float den0 = wself, den1 = 0.f, den2 = 0.f, den3 = 0.f;
    float accA0 = wself * __ldg(&g_H2[d * NCLS + l]);
    float accA1 = 0.f, accA2 = 0.f, accA3 = 0.f;
    float accB0 = (l < 8) ? wself * __ldg(&g_H2[d * NCLS + 32 + l]) : 0.f;
    float accB1 = 0.f, accB2 = 0.f, accB3 = 0.f;

    int e = start;
    for (; e + 3 < end; e += 4) {
        int s0 = __ldg(&g_csr[e]);
        int s1 = __ldg(&g_csr[e + 1]);
        int s2 = __ldg(&g_csr[e + 2]);
        int s3 = __ldg(&g_csr[e + 3]);
        float w0 = __expf(lrelu(__ldg(&g_asrc2[s0]) + adst));
        float w1 = __expf(lrelu(__ldg(&g_asrc2[s1]) + adst));
        float w2 = __expf(lrelu(__ldg(&g_asrc2[s2]) + adst));
        float w3 = __expf(lrelu(__ldg(&g_asrc2[s3]) + adst));
        den0 += w0; den1 += w1; den2 += w2; den3 += w3;
        accA0 += w0 * __ldg(&g_H2[s0 * NCLS + l]);
        accA1 += w1 * __ldg(&g_H2[s1 * NCLS + l]);
        accA2 += w2 * __ldg(&g_H2[s2 * NCLS + l]);
        accA3 += w3 * __ldg(&g_H2[s3 * NCLS + l]);
        if (l < 8) {
            accB0 += w0 * __ldg(&g_H2[s0 * NCLS + 32 + l]);
            accB1 += w1 * __ldg(&g_H2[s1 * NCLS + 32 + l]);
            accB2 += w2 * __ldg(&g_H2[s2 * NCLS + 32 + l]);
            accB3 += w3 * __ldg(&g_H2[s3 * NCLS + 32 + l]);
        }
    }
    for (; e < end; e++) {
        int s0 = __ldg(&g_csr[e]);
        float w0 = __expf(lrelu(__ldg(&g_asrc2[s0]) + adst));
        den0 += w0;
        accA0 += w0 * __ldg(&g_H2[s0 * NCLS + l]);
        if (l < 8) accB0 += w0 * __ldg(&g_H2[s0 * NCLS + 32 + l]);
    }

    float inv = 1.f / ((den0 + den1) + (den2 + den3));
    out[d * NCLS + l] = ((accA0 + accA1) + (accA2 + accA3)) * inv + b2[l];
    if (l < 8) out[d * NCLS + 32 + l] = ((accB0 + accB1) + (accB2 + accB3)) * inv + b2[32 + l];
    if (l == 0) g_deg[d] = 0;   // restore invariant for next replay
}

// ---------------- launch ----------------
static cudaStream_t g_s2 = nullptr;
static cudaEvent_t g_evFork = nullptr, g_evJoin = nullptr, g_evA = nullptr, g_evG = nullptr;

extern "C" void kernel_launch(void* const* d_in, const int* in_sizes, int n_in,
                              void* d_out, int out_size) {
    const float* x   = (const float*)d_in[0];
    const int*   ei  = (const int*)d_in[1];     // int32 (JAX x64 disabled)
    const float* W1  = (const float*)d_in[2];
    const float* as1 = (const float*)d_in[3];
    const float* ad1 = (const float*)d_in[4];
    const float* b1  = (const float*)d_in[5];
    const float* W2  = (const float*)d_in[6];
    const float* as2 = (const float*)d_in[7];
    const float* ad2 = (const float*)d_in[8];
    const float* b2  = (const float*)d_in[9];
    float* out = (float*)d_out;

    if (g_s2 == nullptr) {
        cudaStreamCreateWithFlags(&g_s2, cudaStreamNonBlocking);
        cudaEventCreateWithFlags(&g_evFork, cudaEventDisableTiming);
        cudaEventCreateWithFlags(&g_evJoin, cudaEventDisableTiming);
        cudaEventCreateWithFlags(&g_evA, cudaEventDisableTiming);
        cudaEventCreateWithFlags(&g_evG, cudaEventDisableTiming);
        cudaFuncSetAttribute(gemm1_mma_kernel,
                             cudaFuncAttributeMaxDynamicSharedMemorySize, SM_WORDS * 4);
        cudaFuncSetAttribute(gemm2_mma_kernel,
                             cudaFuncAttributeMaxDynamicSharedMemorySize, SM2_WORDS * 4);
    }

    // fork: single-pass padded-CSR fill on side stream (g_deg zeroed by agg2)
    cudaEventRecord(g_evFork, 0);
    cudaStreamWaitEvent(g_s2, g_evFork, 0);
    fill_kernel<<<(EE / 4 + 255) / 256, 256, 0, g_s2>>>(ei);
    cudaEventRecord(g_evJoin, g_s2);

    // main stream: tensor-core GEMM1 with fused attn1
    gemm1_mma_kernel<<<(NN + 127) / 128, 256, SM_WORDS * 4>>>(x, W1, as1, ad1);

    // join; then pipeline agg1 halves with gemm2 halves
    cudaStreamWaitEvent(0, g_evJoin, 0);
    agg1_kernel<<<(HALF0 * 32) / 256, 256>>>(b1, 0, HALF0);
    cudaEventRecord(g_evA, 0);
    agg1_kernel<<<(HALF1 * 32 + 255) / 256, 256>>>(b1, HALF0, HALF1);

    cudaStreamWaitEvent(g_s2, g_evA, 0);
    gemm2_mma_kernel<<<HALF0 / 128, 256, SM2_WORDS * 4, g_s2>>>(W2, as2, ad2, 0);
    cudaEventRecord(g_evG, g_s2);

    gemm2_mma_kernel<<<(NN + 127) / 128 - HALF0 / 128, 256, SM2_WORDS * 4>>>(W2, as2, ad2, HALF0 / 128);
    cudaStreamWaitEvent(0, g_evG, 0);
    agg2_kernel<<<(NN * 32 + 255) / 256, 256>>>(b2, out);
}

// round 15
// speedup vs baseline: 1.0762x; 1.0034x over previous
#include <cuda_runtime.h>
#include <cuda_bf16.h>
#include <cstdint>

#define NN 50000
#define EE 800000
#define NCLS 40
#define SLOT 128     // padded CSR slots per node; P(deg>128) ~ 1e-80
#define HALF0 25088  // 196 tiles of 128
#define HALF1 (NN - HALF0)
#define LOG2E 1.4426950408889634f

// ---------------- device scratch (static, allocation-free) ----------------
__device__ __align__(16) float g_H1[NN * 128];    // layer1 features (fp32)
__device__ __align__(16) float g_out1[NN * 128];  // layer1 output after ELU
__device__ __align__(16) float g_H2[NN * NCLS];   // layer2 features
__device__ __align__(16) float g_asrc1[NN * 8];   // logits pre-scaled by log2(e)
__device__ __align__(16) float g_adst1[NN * 8];
__device__ float g_asrc2[NN];
__device__ float g_adst2[NN];
__device__ int g_deg[NN];          // zeroed by agg2 each replay (starts zero)
__device__ int g_csr[NN * SLOT];   // padded CSR

__device__ __forceinline__ float lrelu(float x) { return fmaxf(x, 0.2f * x); }
__device__ __forceinline__ float ex2(float x) {
    float r;
    asm("ex2.approx.ftz.f32 %0, %1;" : "=f"(r) : "f"(x));
    return r;
}

// ---------------- CSR build: single pass into padded slots ----------------
__global__ void fill_kernel(const int* __restrict__ ei) {
    int q = blockIdx.x * blockDim.x + threadIdx.x;
    if (q < EE / 4) {
        int4 s4 = __ldg((const int4*)ei + q);
        int4 d4 = __ldg((const int4*)(ei + EE) + q);
        int p0 = atomicAdd(&g_deg[d4.x], 1);
        int p1 = atomicAdd(&g_deg[d4.y], 1);
        int p2 = atomicAdd(&g_deg[d4.z], 1);
        int p3 = atomicAdd(&g_deg[d4.w], 1);
        g_csr[(d4.x << 7) + p0] = s4.x;
        g_csr[(d4.y << 7) + p1] = s4.y;
        g_csr[(d4.z << 7) + p2] = s4.z;
        g_csr[(d4.w << 7) + p3] = s4.w;
    }
}

// ---------------- shared MMA helpers ----------------
__device__ __forceinline__ void mma_bf16(float* c, const uint32_t* a, uint32_t b0, uint32_t b1) {
    asm volatile(
        "mma.sync.aligned.m16n8k16.row.col.f32.bf16.bf16.f32 "
        "{%0,%1,%2,%3}, {%4,%5,%6,%7}, {%8,%9}, {%0,%1,%2,%3};"
        : "+f"(c[0]), "+f"(c[1]), "+f"(c[2]), "+f"(c[3])
        : "r"(a[0]), "r"(a[1]), "r"(a[2]), "r"(a[3]), "r"(b0), "r"(b1));
}

__device__ __forceinline__ uint32_t pack_bf2(float a, float b) {
    __nv_bfloat162 h = __floats2bfloat162_rn(a, b);
    return *(uint32_t*)&h;
}

// ---------------- GEMM1 via mma.sync bf16 (3-term hi/lo split) + fused attn1 ----
#define A_STRIDE 36
#define B_STRIDE 136
#define SM_AHI 0
#define SM_ALO (128 * A_STRIDE)
#define SM_BHI (2 * 128 * A_STRIDE)
#define SM_BLO (2 * 128 * A_STRIDE + 32 * B_STRIDE)
#define SM_WORDS (2 * 128 * A_STRIDE + 2 * 32 * B_STRIDE)

__global__ void __launch_bounds__(256, 2)
gemm1_mma_kernel(const float* __restrict__ x, const float* __restrict__ W1,
                 const float* __restrict__ as, const float* __restrict__ ad) {
    extern __shared__ uint32_t sm[];
    uint32_t* Ahi = sm + SM_AHI;
    uint32_t* Alo = sm + SM_ALO;
    uint32_t* Bhi = sm + SM_BHI;
    uint32_t* Blo = sm + SM_BLO;

    int t = threadIdx.x, wid = t >> 5, lane = t & 31;
    int wr = wid & 3, wc = wid >> 2;
    int nbase = blockIdx.x * 128;

    float c[2][8][4];
#pragma unroll
    for (int rs = 0; rs < 2; rs++)
#pragma unroll
        for (int nf = 0; nf < 8; nf++)
#pragma unroll
            for (int q = 0; q < 4; q++) c[rs][nf][q] = 0.f;

    for (int kc = 0; kc < 2; kc++) {
        if (kc) __syncthreads();
#pragma unroll
        for (int i = 0; i < 8; i++) {
            int idx = t + 256 * i;
            int r = idx >> 4, c4 = idx & 15;
            int node = nbase + r;
            float4 v = make_float4(0.f, 0.f, 0.f, 0.f);
            if (node < NN) v = ((const float4*)x)[node * 32 + kc * 16 + c4];
            uint32_t h0 = pack_bf2(v.x, v.y), h1 = pack_bf2(v.z, v.w);
            __nv_bfloat162 hh0 = *(__nv_bfloat162*)&h0;
            __nv_bfloat162 hh1 = *(__nv_bfloat162*)&h1;
            uint32_t l0 = pack_bf2(v.x - __bfloat162float(hh0.x), v.y - __bfloat162float(hh0.y));
            uint32_t l1 = pack_bf2(v.z - __bfloat162float(hh1.x), v.w - __bfloat162float(hh1.y));
            int w = r * A_STRIDE + c4 * 2;
            Ahi[w] = h0; Ahi[w + 1] = h1;
            Alo[w] = l0; Alo[w + 1] = l1;
        }
#pragma unroll
        for (int i = 0; i < 32; i++) {
            int idx = t + 256 * i;
            int k = idx >> 7, j = idx & 127;
            float w = W1[(kc * 64 + k) * 128 + j];
            __nv_bfloat16 hi = __float2bfloat16(w);
            __nv_bfloat16 lo = __float2bfloat16(w - __bfloat162float(hi));
            int word = (k >> 1) * B_STRIDE + j;
            ((__nv_bfloat16*)(Bhi + word))[k & 1] = hi;
            ((__nv_bfloat16*)(Blo + word))[k & 1] = lo;
        }
        __syncthreads();

#pragma unroll
        for (int kk = 0; kk < 4; kk++) {
            uint32_t ah[2][4], al[2][4];
#pragma unroll
            for (int rs = 0; rs < 2; rs++) {
                int row = wr * 32 + rs * 16 + (lane >> 2);
                int base = row * A_STRIDE + kk * 8 + (lane & 3);
                ah[rs][0] = Ahi[base];
                ah[rs][1] = Ahi[base + 8 * A_STRIDE];
                ah[rs][2] = Ahi[base + 4];
                ah[rs][3] = Ahi[base + 8 * A_STRIDE + 4];
                al[rs][0] = Alo[base];
                al[rs][1] = Alo[base + 8 * A_STRIDE];
                al[rs][2] = Alo[base + 4];
                al[rs][3] = Alo[base + 8 * A_STRIDE + 4];
            }
#pragma unroll
            for (int nf = 0; nf < 8; nf++) {
                int j = wc * 64 + nf * 8 + (lane >> 2);
                int bw = (kk * 8 + (lane & 3)) * B_STRIDE + j;
                uint32_t bh0 = Bhi[bw], bh1 = Bhi[bw + 4 * B_STRIDE];
                uint32_t bl0 = Blo[bw], bl1 = Blo[bw + 4 * B_STRIDE];
#pragma unroll
                for (int rs = 0; rs < 2; rs++) {
                    mma_bf16(c[rs][nf], ah[rs], bh0, bh1);
                    mma_bf16(c[rs][nf], ah[rs], bl0, bl1);
                    mma_bf16(c[rs][nf], al[rs], bh0, bh1);
                }
            }
        }
    }

#pragma unroll
    for (int rs = 0; rs < 2; rs++) {
#pragma unroll
        for (int hh = 0; hh < 2; hh++) {
            int row = wr * 32 + rs * 16 + (lane >> 2) + hh * 8;
            int node = nbase + row;
            float ss[4] = {0.f, 0.f, 0.f, 0.f};
            float dd[4] = {0.f, 0.f, 0.f, 0.f};
#pragma unroll
            for (int nf = 0; nf < 8; nf++) {
                float v0 = c[rs][nf][hh * 2];
                float v1 = c[rs][nf][hh * 2 + 1];
                int col = wc * 64 + nf * 8 + (lane & 3) * 2;
                if (node < NN)
                    *(float2*)&g_H1[node * 128 + col] = make_float2(v0, v1);
                int hp = nf >> 1;
                int wcol = (nf & 1) * 8 + (lane & 3) * 2;
                int hb = (wc * 4 + hp) * 16 + wcol;
                ss[hp] += v0 * __ldg(&as[hb]) + v1 * __ldg(&as[hb + 1]);
                dd[hp] += v0 * __ldg(&ad[hb]) + v1 * __ldg(&ad[hb + 1]);
            }
#pragma unroll
            for (int hp = 0; hp < 4; hp++) {
                ss[hp] += __shfl_xor_sync(0xffffffffu, ss[hp], 1);
                ss[hp] += __shfl_xor_sync(0xffffffffu, ss[hp], 2);
                dd[hp] += __shfl_xor_sync(0xffffffffu, dd[hp], 1);
                dd[hp] += __shfl_xor_sync(0xffffffffu, dd[hp], 2);
            }
            if ((lane & 3) == 0 && node < NN) {
#pragma unroll
                for (int hp = 0; hp < 4; hp++) {
                    g_asrc1[node * 8 + wc * 4 + hp] = ss[hp] * LOG2E;
                    g_adst1[node * 8 + wc * 4 + hp] = dd[hp] * LOG2E;
                }
            }
        }
    }
}

// ---------------- layer-1 aggregation: warp per dst, unroll 8, int4 csr --------
__global__ void __launch_bounds__(256, 5)
agg1_kernel(const float* __restrict__ b1, int base, int cnt) {
    int w = base + ((blockIdx.x * blockDim.x + threadIdx.x) >> 5);
    int l = threadIdx.x & 31;
    if (w >= base + cnt || w >= NN) return;
    int d = w;
    int start = d << 7;
    int end = start + __ldg(&g_deg[d]);
    int hl = l >> 2;

    float adh = __ldg(&g_adst1[d * 8 + hl]);
    float wself = ex2(lrelu(__ldg(&g_asrc1[d * 8 + hl]) + adh));

    float den0 = wself, den1 = 0.f, den2 = 0.f, den3 = 0.f;
    float4 acc0, acc1, acc2, acc3;
    {
        float4 v = __ldg(((const float4*)g_H1) + d * 32 + l);
        acc0.x = wself * v.x; acc0.y = wself * v.y;
        acc0.z = wself * v.z; acc0.w = wself * v.w;
        acc1 = make_float4(0.f, 0.f, 0.f, 0.f);
        acc2 = make_float4(0.f, 0.f, 0.f, 0.f);
        acc3 = make_float4(0.f, 0.f, 0.f, 0.f);
    }

    int e = start;
    for (; e + 7 < end; e += 8) {
        int4 ca = __ldg((const int4*)(g_csr + e));
        int4 cb = __ldg((const int4*)(g_csr + e + 4));
        float w0 = ex2(lrelu(__ldg(&g_asrc1[ca.x * 8 + hl]) + adh));
        float w1 = ex2(lrelu(__ldg(&g_asrc1[ca.y * 8 + hl]) + adh));
        float w2 = ex2(lrelu(__ldg(&g_asrc1[ca.z * 8 + hl]) + adh));
        float w3 = ex2(lrelu(__ldg(&g_asrc1[ca.w * 8 + hl]) + adh));
        float w4 = ex2(lrelu(__ldg(&g_asrc1[cb.x * 8 + hl]) + adh));
        float w5 = ex2(lrelu(__ldg(&g_asrc1[cb.y * 8 + hl]) + adh));
        float w6 = ex2(lrelu(__ldg(&g_asrc1[cb.z * 8 + hl]) + adh));
        float w7 = ex2(lrelu(__ldg(&g_asrc1[cb.w * 8 + hl]) + adh));
        float4 v0 = __ldg(((const float4*)g_H1) + ca.x * 32 + l);
        float4 v1 = __ldg(((const float4*)g_H1) + ca.y * 32 + l);
        float4 v2 = __ldg(((const float4*)g_H1) + ca.z * 32 + l);
        float4 v3 = __ldg(((const float4*)g_H1) + ca.w * 32 + l);
        float4 v4 = __ldg(((const float4*)g_H1) + cb.x * 32 + l);
        float4 v5 = __ldg(((const float4*)g_H1) + cb.y * 32 + l);
        float4 v6 = __ldg(((const float4*)g_H1) + cb.z * 32 + l);
        float4 v7 = __ldg(((const float4*)g_H1) + cb.w * 32 + l);
        den0 += w0 + w4; den1 += w1 + w5; den2 += w2 + w6; den3 += w3 + w7;
        acc0.x += w0 * v0.x + w4 * v4.x; acc0.y += w0 * v0.y + w4 * v4.y;
        acc0.z += w0 * v0.z + w4 * v4.z; acc0.w += w0 * v0.w + w4 * v4.w;
        acc1.x += w1 * v1.x + w5 * v5.x; acc1.y += w1 * v1.y + w5 * v5.y;
        acc1.z += w1 * v1.z + w5 * v5.z; acc1.w += w1 * v1.w + w5 * v5.w;
        acc2.x += w2 * v2.x + w6 * v6.x; acc2.y += w2 * v2.y + w6 * v6.y;
        acc2.z += w2 * v2.z + w6 * v6.z; acc2.w += w2 * v2.w + w6 * v6.w;
        acc3.x += w3 * v3.x + w7 * v7.x; acc3.y += w3 * v3.y + w7 * v7.y;
        acc3.z += w3 * v3.z + w7 * v7.z; acc3.w += w3 * v3.w + w7 * v7.w;
    }
    for (; e < end; e++) {
        int s0 = __ldg(&g_csr[e]);
        float w0 = ex2(lrelu(__ldg(&g_asrc1[s0 * 8 + hl]) + adh));
        float4 v0 = __ldg(((const float4*)g_H1) + s0 * 32 + l);
        den0 += w0;
        acc0.x += w0 * v0.x; acc0.y += w0 * v0.y;
        acc0.z += w0 * v0.z; acc0.w += w0 * v0.w;
    }

    float inv = 1.f / ((den0 + den1) + (den2 + den3));
    float4 bb = ((const float4*)b1)[l];
    float4 r;
    r.x = ((acc0.x + acc1.x) + (acc2.x + acc3.x)) * inv + bb.x;
    r.y = ((acc0.y + acc1.y) + (acc2.y + acc3.y)) * inv + bb.y;
    r.z = ((acc0.z + acc1.z) + (acc2.z + acc3.z)) * inv + bb.z;
    r.w = ((acc0.w + acc1.w) + (acc2.w + acc3.w)) * inv + bb.w;
    r.x = r.x > 0.f ? r.x : __expf(r.x) - 1.f;
    r.y = r.y > 0.f ? r.y : __expf(r.y) - 1.f;
    r.z = r.z > 0.f ? r.z : __expf(r.z) - 1.f;
    r.w = r.w > 0.f ? r.w : __expf(r.w) - 1.f;
    ((float4*)g_out1)[d * 32 + l] = r;
}

// ---------------- GEMM2 via mma.sync bf16 split + fused attn2 (tile offset) ----
#define A2_STRIDE 68
#define B2_STRIDE 44
#define SM2_ALO (128 * A2_STRIDE)
#define SM2_BHI (2 * 128 * A2_STRIDE)
#define SM2_BLO (2 * 128 * A2_STRIDE + 64 * B2_STRIDE)
#define SM2_WORDS (2 * 128 * A2_STRIDE + 2 * 64 * B2_STRIDE)

__global__ void __launch_bounds__(256, 2)
gemm2_mma_kernel(const float* __restrict__ W2,
                 const float* __restrict__ as2, const float* __restrict__ ad2,
                 int tile0) {
    extern __shared__ uint32_t sm[];
    uint32_t* Ahi = sm;
    uint32_t* Alo = sm + SM2_ALO;
    uint32_t* Bhi = sm + SM2_BHI;
    uint32_t* Blo = sm + SM2_BLO;

    int t = threadIdx.x, wid = t >> 5, lane = t & 31;
    int nbase = (tile0 + blockIdx.x) * 128;

#pragma unroll
    for (int i = 0; i < 16; i++) {
        int idx = t + 256 * i;
        int r = idx >> 5, c4 = idx & 31;
        int node = nbase + r;
        float4 v = make_float4(0.f, 0.f, 0.f, 0.f);
        if (node < NN) v = ((const float4*)g_out1)[node * 32 + c4];
        uint32_t h0 = pack_bf2(v.x, v.y), h1 = pack_bf2(v.z, v.w);
        __nv_bfloat162 hh0 = *(__nv_bfloat162*)&h0;
        __nv_bfloat162 hh1 = *(__nv_bfloat162*)&h1;
        uint32_t l0 = pack_bf2(v.x - __bfloat162float(hh0.x), v.y - __bfloat162float(hh0.y));
        uint32_t l1 = pack_bf2(v.z - __bfloat162float(hh1.x), v.w - __bfloat162float(hh1.y));
        int w = r * A2_STRIDE + c4 * 2;
        Ahi[w] = h0; Ahi[w + 1] = h1;
        Alo[w] = l0; Alo[w + 1] = l1;
    }
    for (int idx = t; idx < 128 * NCLS; idx += 256) {
        int k = idx / NCLS, j = idx % NCLS;
        float w = W2[idx];
        __nv_bfloat16 hi = __float2bfloat16(w);
        __nv_bfloat16 lo = __float2bfloat16(w - __bfloat162float(hi));
        int word = (k >> 1) * B2_STRIDE + j;
        ((__nv_bfloat16*)(Bhi + word))[k & 1] = hi;
        ((__nv_bfloat16*)(Blo + word))[k & 1] = lo;
    }
    __syncthreads();

    float c[5][4];
#pragma unroll
    for (int nf = 0; nf < 5; nf++)
#pragma unroll
        for (int q = 0; q < 4; q++) c[nf][q] = 0.f;

#pragma unroll
    for (int kk = 0; kk < 8; kk++) {
        int base = (wid * 16 + (lane >> 2)) * A2_STRIDE + kk * 8 + (lane & 3);
        uint32_t ah[4], al[4];
        ah[0] = Ahi[base];
        ah[1] = Ahi[base + 8 * A2_STRIDE];
        ah[2] = Ahi[base + 4];
        ah[3] = Ahi[base + 8 * A2_STRIDE + 4];
        al[0] = Alo[base];
        al[1] = Alo[base + 8 * A2_STRIDE];
        al[2] = Alo[base + 4];
        al[3] = Alo[base + 8 * A2_STRIDE + 4];
#pragma unroll
        for (int nf = 0; nf < 5; nf++) {
            int j = nf * 8 + (lane >> 2);
            int bw = (kk * 8 + (lane & 3)) * B2_STRIDE + j;
            uint32_t bh0 = Bhi[bw], bh1 = Bhi[bw + 4 * B2_STRIDE];
            uint32_t bl0 = Blo[bw], bl1 = Blo[bw + 4 * B2_STRIDE];
            mma_bf16(c[nf], ah, bh0, bh1);
            mma_bf16(c[nf], ah, bl0, bl1);
            mma_bf16(c[nf], al, bh0, bh1);
        }
    }

#pragma unroll
    for (int hh = 0; hh < 2; hh++) {
        int row = wid * 16 + (lane >> 2) + hh * 8;
        int node = nbase + row;
        float ps = 0.f, pd = 0.f;
#pragma unroll
        for (int nf = 0; nf < 5; nf++) {
            float v0 = c[nf][hh * 2];
            float v1 = c[nf][hh * 2 + 1];
            int col = nf * 8 + (lane & 3) * 2;
            if (node < NN)
                *(float2*)&g_H2[node * NCLS + col] = make_float2(v0, v1);
            ps += v0 * __ldg(&as2[col]) + v1 * __ldg(&as2[col + 1]);
            pd += v0 * __ldg(&ad2[col]) + v1 * __ldg(&ad2[col + 1]);
        }
        ps += __shfl_xor_sync(0xffffffffu, ps, 1);
        ps += __shfl_xor_sync(0xffffffffu, ps, 2);
        pd += __shfl_xor_sync(0xffffffffu, pd, 1);
        pd += __shfl_xor_sync(0xffffffffu, pd, 2);
        if ((lane & 3) == 0 && node < NN) {
            g_asrc2[node] = ps * LOG2E;
            g_adst2[node] = pd * LOG2E;
        }
    }
}

// ---------------- layer-2 aggregation: warp per dst, int4 csr; resets g_deg -----
__global__ void __launch_bounds__(256, 5)
agg2_kernel(const float* __restrict__ b2, float* __restrict__ out) {
    int w = (blockIdx.x * blockDim.x + threadIdx.x) >> 5;
    int l = threadIdx.x & 31;
    if (w >= NN) return;
    int d = w;
    int start = d << 7;
    int deg = __ldg(&g_deg[d]);
    int end = start + deg;

    float adst = __ldg(&g_adst2[d]);
    float wself = ex2(lrelu(__ldg(&g_asrc2[d]) + adst));

    float den0 = wself, den1 = 0.f, den2 = 0.f, den3 = 0.f;
    float accA0 = wself * __ldg(&g_H2[d * NCLS + l]);
    float accA1 = 0.f, accA2 = 0.f, accA3 = 0.f;
    float accB0 = (l < 8) ? wself * __ldg(&g_H2[d * NCLS + 32 + l]) : 0.f;
    float accB1 = 0.f, accB2 = 0.f, accB3 = 0.f;

    int e = start;
    for (; e + 3 < end; e += 4) {
        int4 c4v = __ldg((const int4*)(g_csr + e));
        float w0 = ex2(lrelu(__ldg(&g_asrc2[c4v.x]) + adst));
        float w1 = ex2(lrelu(__ldg(&g_asrc2[c4v.y]) + adst));
        float w2 = ex2(lrelu(__ldg(&g_asrc2[c4v.z]) + adst));
        float w3 = ex2(lrelu(__ldg(&g_asrc2[c4v.w]) + adst));
        den0 += w0; den1 += w1; den2 += w2; den3 += w3;
        accA0 += w0 * __ldg(&g_H2[c4v.x * NCLS + l]);
        accA1 += w1 * __ldg(&g_H2[c4v.y * NCLS + l]);
        accA2 += w2 * __ldg(&g_H2[c4v.z * NCLS + l]);
        accA3 += w3 * __ldg(&g_H2[c4v.w * NCLS + l]);
        if (l < 8) {
            accB0 += w0 * __ldg(&g_H2[c4v.x * NCLS + 32 + l]);
            accB1 += w1 * __ldg(&g_H2[c4v.y * NCLS + 32 + l]);
            accB2 += w2 * __ldg(&g_H2[c4v.z * NCLS + 32 + l]);
            accB3 += w3 * __ldg(&g_H2[c4v.w * NCLS + 32 + l]);
        }
    }
    for (; e < end; e++) {
        int s0 = __ldg(&g_csr[e]);
        float w0 = ex2(lrelu(__ldg(&g_asrc2[s0]) + adst));
        den0 += w0;
        accA0 += w0 * __ldg(&g_H2[s0 * NCLS + l]);
        if (l < 8) accB0 += w0 * __ldg(&g_H2[s0 * NCLS + 32 + l]);
    }

    float inv = 1.f / ((den0 + den1) + (den2 + den3));
    out[d * NCLS + l] = ((accA0 + accA1) + (accA2 + accA3)) * inv + b2[l];
    if (l < 8) out[d * NCLS + 32 + l] = ((accB0 + accB1) + (accB2 + accB3)) * inv + b2[32 + l];
    if (l == 0) g_deg[d] = 0;   // restore invariant for next replay
}

// ---------------- launch ----------------
static cudaStream_t g_s2 = nullptr;
static cudaEvent_t g_evFork = nullptr, g_evJoin = nullptr, g_evA = nullptr, g_evG = nullptr;

extern "C" void kernel_launch(void* const* d_in, const int* in_sizes, int n_in,
                              void* d_out, int out_size) {
    const float* x   = (const float*)d_in[0];
    const int*   ei  = (const int*)d_in[1];     // int32 (JAX x64 disabled)
    const float* W1  = (const float*)d_in[2];
    const float* as1 = (const float*)d_in[3];
    const float* ad1 = (const float*)d_in[4];
    const float* b1  = (const float*)d_in[5];
    const float* W2  = (const float*)d_in[6];
    const float* as2 = (const float*)d_in[7];
    const float* ad2 = (const float*)d_in[8];
    const float* b2  = (const float*)d_in[9];
    float* out = (float*)d_out;

    if (g_s2 == nullptr) {
        cudaStreamCreateWithFlags(&g_s2, cudaStreamNonBlocking);
        cudaEventCreateWithFlags(&g_evFork, cudaEventDisableTiming);
        cudaEventCreateWithFlags(&g_evJoin, cudaEventDisableTiming);
        cudaEventCreateWithFlags(&g_evA, cudaEventDisableTiming);
        cudaEventCreateWithFlags(&g_evG, cudaEventDisableTiming);
        cudaFuncSetAttribute(gemm1_mma_kernel,
                             cudaFuncAttributeMaxDynamicSharedMemorySize, SM_WORDS * 4);
        cudaFuncSetAttribute(gemm2_mma_kernel,
                             cudaFuncAttributeMaxDynamicSharedMemorySize, SM2_WORDS * 4);
    }

    // fork: single-pass padded-CSR fill on side stream (g_deg zeroed by agg2)
    cudaEventRecord(g_evFork, 0);
    cudaStreamWaitEvent(g_s2, g_evFork, 0);
    fill_kernel<<<(EE / 4 + 255) / 256, 256, 0, g_s2>>>(ei);
    cudaEventRecord(g_evJoin, g_s2);

    // main stream: tensor-core GEMM1 with fused attn1
    gemm1_mma_kernel<<<(NN + 127) / 128, 256, SM_WORDS * 4>>>(x, W1, as1, ad1);

    // join; then pipeline agg1 halves with gemm2 halves
    cudaStreamWaitEvent(0, g_evJoin, 0);
    agg1_kernel<<<(HALF0 * 32) / 256, 256>>>(b1, 0, HALF0);
    cudaEventRecord(g_evA, 0);
    agg1_kernel<<<(HALF1 * 32 + 255) / 256, 256>>>(b1, HALF0, HALF1);

    cudaStreamWaitEvent(g_s2, g_evA, 0);
    gemm2_mma_kernel<<<HALF0 / 128, 256, SM2_WORDS * 4, g_s2>>>(W2, as2, ad2, 0);
    cudaEventRecord(g_evG, g_s2);

    gemm2_mma_kernel<<<(NN + 127) / 128 - HALF0 / 128, 256, SM2_WORDS * 4>>>(W2, as2, ad2, HALF0 / 128);
    cudaStreamWaitEvent(0, g_evG, 0);
    agg2_kernel<<<(NN * 32 + 255) / 256, 256>>>(b2, out);
}

// round 16
// speedup vs baseline: 1.1353x; 1.0549x over previous
#include <cuda_runtime.h>
#include <cuda_bf16.h>
#include <cstdint>

#define NN 50000
#define EE 800000
#define NCLS 40
#define SLOT 128     // padded CSR slots per node; P(deg>128) ~ 1e-80
#define HALF0 25088  // 196 tiles of 128
#define HALF1 (NN - HALF0)
#define LOG2E 1.4426950408889634f

#define A_STRIDE 36
#define B_STRIDE 136
#define A2_STRIDE 68
#define B2_STRIDE 44

// ---------------- device scratch (static, allocation-free) ----------------
__device__ __align__(16) float g_H1[NN * 128];    // layer1 features (fp32)
__device__ __align__(16) float g_out1[NN * 128];  // layer1 output after ELU
__device__ __align__(16) float g_H2[NN * NCLS];   // layer2 features
__device__ __align__(16) float g_asrc1[NN * 8];   // logits pre-scaled by log2(e)
__device__ __align__(16) float g_adst1[NN * 8];
__device__ float g_asrc2[NN];
__device__ float g_adst2[NN];
__device__ int g_deg[NN];          // zeroed by agg2 each replay (starts zero)
__device__ int g_csr[NN * SLOT];   // padded CSR
// precomputed bf16 hi/lo weight tiles in smem-ready layout
__device__ __align__(16) uint32_t g_W1h[2][32 * B_STRIDE];
__device__ __align__(16) uint32_t g_W1l[2][32 * B_STRIDE];
__device__ __align__(16) uint32_t g_W2h[64 * B2_STRIDE];
__device__ __align__(16) uint32_t g_W2l[64 * B2_STRIDE];

__device__ __forceinline__ float lrelu(float x) { return fmaxf(x, 0.2f * x); }
__device__ __forceinline__ float ex2(float x) {
    float r;
    asm("ex2.approx.ftz.f32 %0, %1;" : "=f"(r) : "f"(x));
    return r;
}

// ---------------- weight prep: split W1/W2 into bf16 hi/lo tile layouts ------
__global__ void prep_kernel(const float* __restrict__ W1, const float* __restrict__ W2) {
    int i = blockIdx.x * blockDim.x + threadIdx.x;
    if (i < 16384) {                       // W1: 2 chunks x 64 k x 128 j
        int kc = i >> 13, r = i & 8191;
        int k = r >> 7, j = r & 127;
        float w = W1[(kc * 64 + k) * 128 + j];
        __nv_bfloat16 hi = __float2bfloat16(w);
        __nv_bfloat16 lo = __float2bfloat16(w - __bfloat162float(hi));
        int word = (k >> 1) * B_STRIDE + j;
        ((__nv_bfloat16*)(g_W1h[kc] + word))[k & 1] = hi;
        ((__nv_bfloat16*)(g_W1l[kc] + word))[k & 1] = lo;
    } else if (i < 16384 + 5120) {         // W2: 128 k x 40 j
        int r = i - 16384;
        int k = r / NCLS, j = r % NCLS;
        float w = W2[r];
        __nv_bfloat16 hi = __float2bfloat16(w);
        __nv_bfloat16 lo = __float2bfloat16(w - __bfloat162float(hi));
        int word = (k >> 1) * B2_STRIDE + j;
        ((__nv_bfloat16*)(g_W2h + word))[k & 1] = hi;
        ((__nv_bfloat16*)(g_W2l + word))[k & 1] = lo;
    }
}

// ---------------- CSR build: single pass into padded slots ----------------
__global__ void fill_kernel(const int* __restrict__ ei) {
    int q = blockIdx.x * blockDim.x + threadIdx.x;
    if (q < EE / 4) {
        int4 s4 = __ldg((const int4*)ei + q);
        int4 d4 = __ldg((const int4*)(ei + EE) + q);
        int p0 = atomicAdd(&g_deg[d4.x], 1);
        int p1 = atomicAdd(&g_deg[d4.y], 1);
        int p2 = atomicAdd(&g_deg[d4.z], 1);
        int p3 = atomicAdd(&g_deg[d4.w], 1);
        g_csr[(d4.x << 7) + p0] = s4.x;
        g_csr[(d4.y << 7) + p1] = s4.y;
        g_csr[(d4.z << 7) + p2] = s4.z;
        g_csr[(d4.w << 7) + p3] = s4.w;
    }
}

// ---------------- shared MMA helpers ----------------
__device__ __forceinline__ void mma_bf16(float* c, const uint32_t* a, uint32_t b0, uint32_t b1) {
    asm volatile(
        "mma.sync.aligned.m16n8k16.row.col.f32.bf16.bf16.f32 "
        "{%0,%1,%2,%3}, {%4,%5,%6,%7}, {%8,%9}, {%0,%1,%2,%3};"
        : "+f"(c[0]), "+f"(c[1]), "+f"(c[2]), "+f"(c[3])
        : "r"(a[0]), "r"(a[1]), "r"(a[2]), "r"(a[3]), "r"(b0), "r"(b1));
}

__device__ __forceinline__ uint32_t pack_bf2(float a, float b) {
    __nv_bfloat162 h = __floats2bfloat162_rn(a, b);
    return *(uint32_t*)&h;
}

// ---------------- GEMM1 via mma.sync bf16 (3-term hi/lo split) + fused attn1 ----
#define SM_AHI 0
#define SM_ALO (128 * A_STRIDE)
#define SM_BHI (2 * 128 * A_STRIDE)
#define SM_BLO (2 * 128 * A_STRIDE + 32 * B_STRIDE)
#define SM_WORDS (2 * 128 * A_STRIDE + 2 * 32 * B_STRIDE)

__global__ void __launch_bounds__(256, 2)
gemm1_mma_kernel(const float* __restrict__ x,
                 const float* __restrict__ as, const float* __restrict__ ad) {
    extern __shared__ uint32_t sm[];
    uint32_t* Ahi = sm + SM_AHI;
    uint32_t* Alo = sm + SM_ALO;
    uint32_t* Bhi = sm + SM_BHI;
    uint32_t* Blo = sm + SM_BLO;

    int t = threadIdx.x, wid = t >> 5, lane = t & 31;
    int wr = wid & 3, wc = wid >> 2;
    int nbase = blockIdx.x * 128;

    float c[2][8][4];
#pragma unroll
    for (int rs = 0; rs < 2; rs++)
#pragma unroll
        for (int nf = 0; nf < 8; nf++)
#pragma unroll
            for (int q = 0; q < 4; q++) c[rs][nf][q] = 0.f;

    for (int kc = 0; kc < 2; kc++) {
        if (kc) __syncthreads();
#pragma unroll
        for (int i = 0; i < 8; i++) {
            int idx = t + 256 * i;
            int r = idx >> 4, c4 = idx & 15;
            int node = nbase + r;
            float4 v = make_float4(0.f, 0.f, 0.f, 0.f);
            if (node < NN) v = ((const float4*)x)[node * 32 + kc * 16 + c4];
            uint32_t h0 = pack_bf2(v.x, v.y), h1 = pack_bf2(v.z, v.w);
            __nv_bfloat162 hh0 = *(__nv_bfloat162*)&h0;
            __nv_bfloat162 hh1 = *(__nv_bfloat162*)&h1;
            uint32_t l0 = pack_bf2(v.x - __bfloat162float(hh0.x), v.y - __bfloat162float(hh0.y));
            uint32_t l1 = pack_bf2(v.z - __bfloat162float(hh1.x), v.w - __bfloat162float(hh1.y));
            int w = r * A_STRIDE + c4 * 2;
            Ahi[w] = h0; Ahi[w + 1] = h1;
            Alo[w] = l0; Alo[w + 1] = l1;
        }
        // copy precomputed W1 tiles (int4)
#pragma unroll
        for (int i = 0; i < 5; i++) {
            int idx = t + 256 * i;           // 1088 int4 per buffer
            if (idx < 1088) {
                ((int4*)Bhi)[idx] = __ldg((const int4*)g_W1h[kc] + idx);
                ((int4*)Blo)[idx] = __ldg((const int4*)g_W1l[kc] + idx);
            }
        }
        __syncthreads();

#pragma unroll
        for (int kk = 0; kk < 4; kk++) {
            uint32_t ah[2][4], al[2][4];
#pragma unroll
            for (int rs = 0; rs < 2; rs++) {
                int row = wr * 32 + rs * 16 + (lane >> 2);
                int base = row * A_STRIDE + kk * 8 + (lane & 3);
                ah[rs][0] = Ahi[base];
                ah[rs][1] = Ahi[base + 8 * A_STRIDE];
                ah[rs][2] = Ahi[base + 4];
                ah[rs][3] = Ahi[base + 8 * A_STRIDE + 4];
                al[rs][0] = Alo[base];
                al[rs][1] = Alo[base + 8 * A_STRIDE];
                al[rs][2] = Alo[base + 4];
                al[rs][3] = Alo[base + 8 * A_STRIDE + 4];
            }
#pragma unroll
            for (int nf = 0; nf < 8; nf++) {
                int j = wc * 64 + nf * 8 + (lane >> 2);
                int bw = (kk * 8 + (lane & 3)) * B_STRIDE + j;
                uint32_t bh0 = Bhi[bw], bh1 = Bhi[bw + 4 * B_STRIDE];
                uint32_t bl0 = Blo[bw], bl1 = Blo[bw + 4 * B_STRIDE];
#pragma unroll
                for (int rs = 0; rs < 2; rs++) {
                    mma_bf16(c[rs][nf], ah[rs], bh0, bh1);
                    mma_bf16(c[rs][nf], ah[rs], bl0, bl1);
                    mma_bf16(c[rs][nf], al[rs], bh0, bh1);
                }
            }
        }
    }

#pragma unroll
    for (int rs = 0; rs < 2; rs++) {
#pragma unroll
        for (int hh = 0; hh < 2; hh++) {
            int row = wr * 32 + rs * 16 + (lane >> 2) + hh * 8;
            int node = nbase + row;
            float ss[4] = {0.f, 0.f, 0.f, 0.f};
            float dd[4] = {0.f, 0.f, 0.f, 0.f};
#pragma unroll
            for (int nf = 0; nf < 8; nf++) {
                float v0 = c[rs][nf][hh * 2];
                float v1 = c[rs][nf][hh * 2 + 1];
                int col = wc * 64 + nf * 8 + (lane & 3) * 2;
                if (node < NN)
                    *(float2*)&g_H1[node * 128 + col] = make_float2(v0, v1);
                int hp = nf >> 1;
                int wcol = (nf & 1) * 8 + (lane & 3) * 2;
                int hb = (wc * 4 + hp) * 16 + wcol;
                ss[hp] += v0 * __ldg(&as[hb]) + v1 * __ldg(&as[hb + 1]);
                dd[hp] += v0 * __ldg(&ad[hb]) + v1 * __ldg(&ad[hb + 1]);
            }
#pragma unroll
            for (int hp = 0; hp < 4; hp++) {
                ss[hp] += __shfl_xor_sync(0xffffffffu, ss[hp], 1);
                ss[hp] += __shfl_xor_sync(0xffffffffu, ss[hp], 2);
                dd[hp] += __shfl_xor_sync(0xffffffffu, dd[hp], 1);
                dd[hp] += __shfl_xor_sync(0xffffffffu, dd[hp], 2);
            }
            if ((lane & 3) == 0 && node < NN) {
#pragma unroll
                for (int hp = 0; hp < 4; hp++) {
                    g_asrc1[node * 8 + wc * 4 + hp] = ss[hp] * LOG2E;
                    g_adst1[node * 8 + wc * 4 + hp] = dd[hp] * LOG2E;
                }
            }
        }
    }
}

// ---------------- layer-1 aggregation: warp per dst, unroll 8, int4 csr --------
__global__ void __launch_bounds__(256, 5)
agg1_kernel(const float* __restrict__ b1, int base, int cnt) {
    int w = base + ((blockIdx.x * blockDim.x + threadIdx.x) >> 5);
    int l = threadIdx.x & 31;
    if (w >= base + cnt || w >= NN) return;
    int d = w;
    int start = d << 7;
    int end = start + __ldg(&g_deg[d]);
    int hl = l >> 2;

    float adh = __ldg(&g_adst1[d * 8 + hl]);
    float wself = ex2(lrelu(__ldg(&g_asrc1[d * 8 + hl]) + adh));

    float den0 = wself, den1 = 0.f, den2 = 0.f, den3 = 0.f;
    float4 acc0, acc1, acc2, acc3;
    {
        float4 v = __ldg(((const float4*)g_H1) + d * 32 + l);
        acc0.x = wself * v.x; acc0.y = wself * v.y;
        acc0.z = wself * v.z; acc0.w = wself * v.w;
        acc1 = make_float4(0.f, 0.f, 0.f, 0.f);
        acc2 = make_float4(0.f, 0.f, 0.f, 0.f);
        acc3 = make_float4(0.f, 0.f, 0.f, 0.f);
    }

    int e = start;
    for (; e + 7 < end; e += 8) {
        int4 ca = __ldg((const int4*)(g_csr + e));
        int4 cb = __ldg((const int4*)(g_csr + e + 4));
        float w0 = ex2(lrelu(__ldg(&g_asrc1[ca.x * 8 + hl]) + adh));
        float w1 = ex2(lrelu(__ldg(&g_asrc1[ca.y * 8 + hl]) + adh));
        float w2 = ex2(lrelu(__ldg(&g_asrc1[ca.z * 8 + hl]) + adh));
        float w3 = ex2(lrelu(__ldg(&g_asrc1[ca.w * 8 + hl]) + adh));
        float w4 = ex2(lrelu(__ldg(&g_asrc1[cb.x * 8 + hl]) + adh));
        float w5 = ex2(lrelu(__ldg(&g_asrc1[cb.y * 8 + hl]) + adh));
        float w6 = ex2(lrelu(__ldg(&g_asrc1[cb.z * 8 + hl]) + adh));
        float w7 = ex2(lrelu(__ldg(&g_asrc1[cb.w * 8 + hl]) + adh));
        float4 v0 = __ldg(((const float4*)g_H1) + ca.x * 32 + l);
        float4 v1 = __ldg(((const float4*)g_H1) + ca.y * 32 + l);
        float4 v2 = __ldg(((const float4*)g_H1) + ca.z * 32 + l);
        float4 v3 = __ldg(((const float4*)g_H1) + ca.w * 32 + l);
        float4 v4 = __ldg(((const float4*)g_H1) + cb.x * 32 + l);
        float4 v5 = __ldg(((const float4*)g_H1) + cb.y * 32 + l);
        float4 v6 = __ldg(((const float4*)g_H1) + cb.z * 32 + l);
        float4 v7 = __ldg(((const float4*)g_H1) + cb.w * 32 + l);
        den0 += w0 + w4; den1 += w1 + w5; den2 += w2 + w6; den3 += w3 + w7;
        acc0.x += w0 * v0.x + w4 * v4.x; acc0.y += w0 * v0.y + w4 * v4.y;
        acc0.z += w0 * v0.z + w4 * v4.z; acc0.w += w0 * v0.w + w4 * v4.w;
        acc1.x += w1 * v1.x + w5 * v5.x; acc1.y += w1 * v1.y + w5 * v5.y;
        acc1.z += w1 * v1.z + w5 * v5.z; acc1.w += w1 * v1.w + w5 * v5.w;
        acc2.x += w2 * v2.x + w6 * v6.x; acc2.y += w2 * v2.y + w6 * v6.y;
        acc2.z += w2 * v2.z + w6 * v6.z; acc2.w += w2 * v2.w + w6 * v6.w;
        acc3.x += w3 * v3.x + w7 * v7.x; acc3.y += w3 * v3.y + w7 * v7.y;
        acc3.z += w3 * v3.z + w7 * v7.z; acc3.w += w3 * v3.w + w7 * v7.w;
    }
    for (; e < end; e++) {
        int s0 = __ldg(&g_csr[e]);
        float w0 = ex2(lrelu(__ldg(&g_asrc1[s0 * 8 + hl]) + adh));
        float4 v0 = __ldg(((const float4*)g_H1) + s0 * 32 + l);
        den0 += w0;
        acc0.x += w0 * v0.x; acc0.y += w0 * v0.y;
        acc0.z += w0 * v0.z; acc0.w += w0 * v0.w;
    }

    float inv = 1.f / ((den0 + den1) + (den2 + den3));
    float4 bb = ((const float4*)b1)[l];
    float4 r;
    r.x = ((acc0.x + acc1.x) + (acc2.x + acc3.x)) * inv + bb.x;
    r.y = ((acc0.y + acc1.y) + (acc2.y + acc3.y)) * inv + bb.y;
    r.z = ((acc0.z + acc1.z) + (acc2.z + acc3.z)) * inv + bb.z;
    r.w = ((acc0.w + acc1.w) + (acc2.w + acc3.w)) * inv + bb.w;
    r.x = r.x > 0.f ? r.x : __expf(r.x) - 1.f;
    r.y = r.y > 0.f ? r.y : __expf(r.y) - 1.f;
    r.z = r.z > 0.f ? r.z : __expf(r.z) - 1.f;
    r.w = r.w > 0.f ? r.w : __expf(r.w) - 1.f;
    ((float4*)g_out1)[d * 32 + l] = r;
}

// ---------------- GEMM2 via mma.sync bf16 split + fused attn2 (tile offset) ----
#define SM2_ALO (128 * A2_STRIDE)
#define SM2_BHI (2 * 128 * A2_STRIDE)
#define SM2_BLO (2 * 128 * A2_STRIDE + 64 * B2_STRIDE)
#define SM2_WORDS (2 * 128 * A2_STRIDE + 2 * 64 * B2_STRIDE)

__global__ void __launch_bounds__(256, 2)
gemm2_mma_kernel(const float* __restrict__ as2, const float* __restrict__ ad2,
                 int tile0) {
    extern __shared__ uint32_t sm[];
    uint32_t* Ahi = sm;
    uint32_t* Alo = sm + SM2_ALO;
    uint32_t* Bhi = sm + SM2_BHI;
    uint32_t* Blo = sm + SM2_BLO;

    int t = threadIdx.x, wid = t >> 5, lane = t & 31;
    int nbase = (tile0 + blockIdx.x) * 128;

#pragma unroll
    for (int i = 0; i < 16; i++) {
        int idx = t + 256 * i;
        int r = idx >> 5, c4 = idx & 31;
        int node = nbase + r;
        float4 v = make_float4(0.f, 0.f, 0.f, 0.f);
        if (node < NN) v = ((const float4*)g_out1)[node * 32 + c4];
        uint32_t h0 = pack_bf2(v.x, v.y), h1 = pack_bf2(v.z, v.w);
        __nv_bfloat162 hh0 = *(__nv_bfloat162*)&h0;
        __nv_bfloat162 hh1 = *(__nv_bfloat162*)&h1;
        uint32_t l0 = pack_bf2(v.x - __bfloat162float(hh0.x), v.y - __bfloat162float(hh0.y));
        uint32_t l1 = pack_bf2(v.z - __bfloat162float(hh1.x), v.w - __bfloat162float(hh1.y));
        int w = r * A2_STRIDE + c4 * 2;
        Ahi[w] = h0; Ahi[w + 1] = h1;
        Alo[w] = l0; Alo[w + 1] = l1;
    }
    // copy precomputed W2 tiles (int4): 704 int4 per buffer
#pragma unroll
    for (int i = 0; i < 3; i++) {
        int idx = t + 256 * i;
        if (idx < 704) {
            ((int4*)Bhi)[idx] = __ldg((const int4*)g_W2h + idx);
            ((int4*)Blo)[idx] = __ldg((const int4*)g_W2l + idx);
        }
    }
    __syncthreads();

    float c[5][4];
#pragma unroll
    for (int nf = 0; nf < 5; nf++)
#pragma unroll
        for (int q = 0; q < 4; q++) c[nf][q] = 0.f;

#pragma unroll
    for (int kk = 0; kk < 8; kk++) {
        int base = (wid * 16 + (lane >> 2)) * A2_STRIDE + kk * 8 + (lane & 3);
        uint32_t ah[4], al[4];
        ah[0] = Ahi[base];
        ah[1] = Ahi[base + 8 * A2_STRIDE];
        ah[2] = Ahi[base + 4];
        ah[3] = Ahi[base + 8 * A2_STRIDE + 4];
        al[0] = Alo[base];
        al[1] = Alo[base + 8 * A2_STRIDE];
        al[2] = Alo[base + 4];
        al[3] = Alo[base + 8 * A2_STRIDE + 4];
#pragma unroll
        for (int nf = 0; nf < 5; nf++) {
            int j = nf * 8 + (lane >> 2);
            int bw = (kk * 8 + (lane & 3)) * B2_STRIDE + j;
            uint32_t bh0 = Bhi[bw], bh1 = Bhi[bw + 4 * B2_STRIDE];
            uint32_t bl0 = Blo[bw], bl1 = Blo[bw + 4 * B2_STRIDE];
            mma_bf16(c[nf], ah, bh0, bh1);
            mma_bf16(c[nf], ah, bl0, bl1);
            mma_bf16(c[nf], al, bh0, bh1);
        }
    }

#pragma unroll
    for (int hh = 0; hh < 2; hh++) {
        int row = wid * 16 + (lane >> 2) + hh * 8;
        int node = nbase + row;
        float ps = 0.f, pd = 0.f;
#pragma unroll
        for (int nf = 0; nf < 5; nf++) {
            float v0 = c[nf][hh * 2];
            float v1 = c[nf][hh * 2 + 1];
            int col = nf * 8 + (lane & 3) * 2;
            if (node < NN)
                *(float2*)&g_H2[node * NCLS + col] = make_float2(v0, v1);
            ps += v0 * __ldg(&as2[col]) + v1 * __ldg(&as2[col + 1]);
            pd += v0 * __ldg(&ad2[col]) + v1 * __ldg(&ad2[col + 1]);
        }
        ps += __shfl_xor_sync(0xffffffffu, ps, 1);
        ps += __shfl_xor_sync(0xffffffffu, ps, 2);
        pd += __shfl_xor_sync(0xffffffffu, pd, 1);
        pd += __shfl_xor_sync(0xffffffffu, pd, 2);
        if ((lane & 3) == 0 && node < NN) {
            g_asrc2[node] = ps * LOG2E;
            g_adst2[node] = pd * LOG2E;
        }
    }
}

// ---------------- layer-2 aggregation: warp per dst, unroll 8; resets g_deg -----
__global__ void __launch_bounds__(256, 5)
agg2_kernel(const float* __restrict__ b2, float* __restrict__ out) {
    int w = (blockIdx.x * blockDim.x + threadIdx.x) >> 5;
    int l = threadIdx.x & 31;
    if (w >= NN) return;
    int d = w;
    int start = d << 7;
    int deg = __ldg(&g_deg[d]);
    int end = start + deg;

    float adst = __ldg(&g_adst2[d]);
    float wself = ex2(lrelu(__ldg(&g_asrc2[d]) + adst));

    float den0 = wself, den1 = 0.f, den2 = 0.f, den3 = 0.f;
    float accA0 = wself * __ldg(&g_H2[d * NCLS + l]);
    float accA1 = 0.f, accA2 = 0.f, accA3 = 0.f;
    float accB0 = (l < 8) ? wself * __ldg(&g_H2[d * NCLS + 32 + l]) : 0.f;
    float accB1 = 0.f, accB2 = 0.f, accB3 = 0.f;

    int e = start;
    for (; e + 7 < end; e += 8) {
        int4 ca = __ldg((const int4*)(g_csr + e));
        int4 cb = __ldg((const int4*)(g_csr + e + 4));
        float w0 = ex2(lrelu(__ldg(&g_asrc2[ca.x]) + adst));
        float w1 = ex2(lrelu(__ldg(&g_asrc2[ca.y]) + adst));
        float w2 = ex2(lrelu(__ldg(&g_asrc2[ca.z]) + adst));
        float w3 = ex2(lrelu(__ldg(&g_asrc2[ca.w]) + adst));
        float w4 = ex2(lrelu(__ldg(&g_asrc2[cb.x]) + adst));
        float w5 = ex2(lrelu(__ldg(&g_asrc2[cb.y]) + adst));
        float w6 = ex2(lrelu(__ldg(&g_asrc2[cb.z]) + adst));
        float w7 = ex2(lrelu(__ldg(&g_asrc2[cb.w]) + adst));
        den0 += w0 + w4; den1 += w1 + w5; den2 += w2 + w6; den3 += w3 + w7;
        accA0 += w0 * __ldg(&g_H2[ca.x * NCLS + l]) + w4 * __ldg(&g_H2[cb.x * NCLS + l]);
        accA1 += w1 * __ldg(&g_H2[ca.y * NCLS + l]) + w5 * __ldg(&g_H2[cb.y * NCLS + l]);
        accA2 += w2 * __ldg(&g_H2[ca.z * NCLS + l]) + w6 * __ldg(&g_H2[cb.z * NCLS + l]);
        accA3 += w3 * __ldg(&g_H2[ca.w * NCLS + l]) + w7 * __ldg(&g_H2[cb.w * NCLS + l]);
        if (l < 8) {
            accB0 += w0 * __ldg(&g_H2[ca.x * NCLS + 32 + l]) + w4 * __ldg(&g_H2[cb.x * NCLS + 32 + l]);
            accB1 += w1 * __ldg(&g_H2[ca.y * NCLS + 32 + l]) + w5 * __ldg(&g_H2[cb.y * NCLS + 32 + l]);
            accB2 += w2 * __ldg(&g_H2[ca.z * NCLS + 32 + l]) + w6 * __ldg(&g_H2[cb.z * NCLS + 32 + l]);
            accB3 += w3 * __ldg(&g_H2[ca.w * NCLS + 32 + l]) + w7 * __ldg(&g_H2[cb.w * NCLS + 32 + l]);
        }
    }
    for (; e < end; e++) {
        int s0 = __ldg(&g_csr[e]);
        float w0 = ex2(lrelu(__ldg(&g_asrc2[s0]) + adst));
        den0 += w0;
        accA0 += w0 * __ldg(&g_H2[s0 * NCLS + l]);
        if (l < 8) accB0 += w0 * __ldg(&g_H2[s0 * NCLS + 32 + l]);
    }

    float inv = 1.f / ((den0 + den1) + (den2 + den3));
    out[d * NCLS + l] = ((accA0 + accA1) + (accA2 + accA3)) * inv + b2[l];
    if (l < 8) out[d * NCLS + 32 + l] = ((accB0 + accB1) + (accB2 + accB3)) * inv + b2[32 + l];
    if (l == 0) g_deg[d] = 0;   // restore invariant for next replay
}

// ---------------- launch ----------------
static cudaStream_t g_s2 = nullptr;
static cudaEvent_t g_evFork = nullptr, g_evJoin = nullptr, g_evA = nullptr, g_evG = nullptr;

extern "C" void kernel_launch(void* const* d_in, const int* in_sizes, int n_in,
                              void* d_out, int out_size) {
    const float* x   = (const float*)d_in[0];
    const int*   ei  = (const int*)d_in[1];     // int32 (JAX x64 disabled)
    const float* W1  = (const float*)d_in[2];
    const float* as1 = (const float*)d_in[3];
    const float* ad1 = (const float*)d_in[4];
    const float* b1  = (const float*)d_in[5];
    const float* W2  = (const float*)d_in[6];
    const float* as2 = (const float*)d_in[7];
    const float* ad2 = (const float*)d_in[8];
    const float* b2  = (const float*)d_in[9];
    float* out = (float*)d_out;

    if (g_s2 == nullptr) {
        cudaStreamCreateWithFlags(&g_s2, cudaStreamNonBlocking);
        cudaEventCreateWithFlags(&g_evFork, cudaEventDisableTiming);
        cudaEventCreateWithFlags(&g_evJoin, cudaEventDisableTiming);
        cudaEventCreateWithFlags(&g_evA, cudaEventDisableTiming);
        cudaEventCreateWithFlags(&g_evG, cudaEventDisableTiming);
        cudaFuncSetAttribute(gemm1_mma_kernel,
                             cudaFuncAttributeMaxDynamicSharedMemorySize, SM_WORDS * 4);
        cudaFuncSetAttribute(gemm2_mma_kernel,
                             cudaFuncAttributeMaxDynamicSharedMemorySize, SM2_WORDS * 4);
    }

    // fork: single-pass padded-CSR fill on side stream (g_deg zeroed by agg2)
    cudaEventRecord(g_evFork, 0);
    cudaStreamWaitEvent(g_s2, g_evFork, 0);
    fill_kernel<<<(EE / 4 + 255) / 256, 256, 0, g_s2>>>(ei);
    cudaEventRecord(g_evJoin, g_s2);

    // main stream: weight prep, then tensor-core GEMM1 with fused attn1
    prep_kernel<<<(16384 + 5120 + 255) / 256, 256>>>(W1, W2);
    gemm1_mma_kernel<<<(NN + 127) / 128, 256, SM_WORDS * 4>>>(x, as1, ad1);

    // join; then pipeline agg1 halves with gemm2 halves
    cudaStreamWaitEvent(0, g_evJoin, 0);
    agg1_kernel<<<(HALF0 * 32) / 256, 256>>>(b1, 0, HALF0);
    cudaEventRecord(g_evA, 0);
    agg1_kernel<<<(HALF1 * 32 + 255) / 256, 256>>>(b1, HALF0, HALF1);

    cudaStreamWaitEvent(g_s2, g_evA, 0);
    gemm2_mma_kernel<<<HALF0 / 128, 256, SM2_WORDS * 4, g_s2>>>(as2, ad2, 0);
    cudaEventRecord(g_evG, g_s2);

    gemm2_mma_kernel<<<(NN + 127) / 128 - HALF0 / 128, 256, SM2_WORDS * 4>>>(as2, ad2, HALF0 / 128);
    cudaStreamWaitEvent(0, g_evG, 0);
    agg2_kernel<<<(NN * 32 + 255) / 256, 256>>>(b2, out);
}